// round 11
// baseline (speedup 1.0000x reference)
#include <cuda_runtime.h>

#define NS 20480
#define EMAX 120000
#define TMAX 2097152
#define DHIST 16384
#define MAXB 160
#define DAMAX 64

__device__ __align__(16) int g_srcHist[NS + 8], g_tgtHist[NS + 8];
__device__ __align__(16) int g_srcBase[NS + 8];
__device__ int g_curA[NS + 8];
__device__ int g_eScat[EMAX], g_ePerm[EMAX];
__device__ int g_tgtS[EMAX];
__device__ __align__(16) int g_prod[NS + 8];
__device__ unsigned int g_cVW[TMAX];               // kept triplets, compacted, (v<<16)|w
__device__ __align__(16) int g_histTri[NS + 8];
__device__ __align__(16) int g_deg[NS + 8];
__device__ int g_deg2[NS + 8];
__device__ __align__(16) int g_keptOut[NS + 8], g_keptInK[NS + 8];
__device__ __align__(16) int g_cntKept[NS + 8];
__device__ int g_kBase[NS + 8];
__device__ __align__(16) int g_histD[DHIST + 8];
__device__ int g_cumD[DHIST + 8];
__device__ int g_maxNode;
__device__ float g_sinkf;
__device__ __align__(16) int g_tieEx[NS + 8];
__device__ int g_keep[NS + 8];
__device__ __align__(16) int g_srcPresent[NS + 8], g_present[NS + 8];
__device__ int g_srcRank[NS + 8], g_rank[NS + 8];
__device__ float g_Wt[3 * 64 * 64];
__device__ volatile int g_arrive[MAXB * 32];
__device__ volatile int g_barPhase;

__device__ __forceinline__ void gridBar(int ep, int nb) {
    __syncthreads();
    if (blockIdx.x == 0) {
        if (threadIdx.x < 32) {
            int lane = threadIdx.x;
            if (lane == 0) { __threadfence(); g_arrive[0] = ep; }
            bool ok;
            do {
                ok = true;
                for (int s = lane; s < nb; s += 32)
                    if (g_arrive[s * 32] < ep) ok = false;
            } while (__ballot_sync(0xffffffffu, !ok));
            if (lane == 0) { __threadfence(); g_barPhase = ep; }
        }
    } else if (threadIdx.x == 0) {
        __threadfence();
        g_arrive[blockIdx.x * 32] = ep;
        while (g_barPhase < ep) __nanosleep(32);
        __threadfence();
    }
    __syncthreads();
}

__device__ __forceinline__ int blockScanEx(int v, int* tot) {
    __shared__ int s_w[32];
    __shared__ int s_tot;
    int lane = threadIdx.x & 31, wid = threadIdx.x >> 5, nw = blockDim.x >> 5;
    int inc = v;
#pragma unroll
    for (int o = 1; o < 32; o <<= 1) {
        int u = __shfl_up_sync(0xffffffffu, inc, o);
        if (lane >= o) inc += u;
    }
    if (lane == 31) s_w[wid] = inc;
    __syncthreads();
    if (wid == 0) {
        int sv2 = (lane < nw) ? s_w[lane] : 0;
        int si = sv2;
#pragma unroll
        for (int o = 1; o < 32; o <<= 1) {
            int u = __shfl_up_sync(0xffffffffu, si, o);
            if (lane >= o) si += u;
        }
        s_w[lane] = si - sv2;
        if (lane == 31) s_tot = si;
    }
    __syncthreads();
    int ex = inc - v + s_w[wid];
    *tot = s_tot;
    __syncthreads();
    return ex;
}

template <int VPT4>
__device__ void sbScanFast(const int* in, int* out, int n) {
    int v[VPT4 * 4];
    const int4* in4 = (const int4*)in;
#pragma unroll
    for (int j = 0; j < VPT4; j++) {
        int4 q = in4[threadIdx.x * VPT4 + j];
        v[4 * j] = q.x; v[4 * j + 1] = q.y; v[4 * j + 2] = q.z; v[4 * j + 3] = q.w;
    }
    int loc = 0;
#pragma unroll
    for (int j = 0; j < VPT4 * 4; j++) { int t = v[j]; v[j] = loc; loc += t; }
    int tot, ex = blockScanEx(loc, &tot);
    int base = threadIdx.x * VPT4 * 4;
#pragma unroll
    for (int j = 0; j < VPT4 * 4; j++) {
        int i = base + j;
        if (i < n) out[i] = ex + v[j];
    }
    if (threadIdx.x == 0) out[n] = tot;
}

__global__ void kBarInit() {
    int i = blockIdx.x * blockDim.x + threadIdx.x;
    if (i < MAXB * 32) g_arrive[i] = 0;
    if (i == 0) g_barPhase = 0;
}

__global__ void __launch_bounds__(1024, 1) kMega(
    const float* __restrict__ x, const int* __restrict__ ei,
    const float* __restrict__ W, const float* __restrict__ bvec,
    float* __restrict__ out, int N, int E)
{
    __shared__ float sv[32][192];
    __shared__ int s_uns[32][DAMAX];
    __shared__ int s_srt[32][DAMAX];
    __shared__ int s_eb[32][DAMAX];
    __shared__ int s_dn[32][DAMAX];
    __shared__ int s_kv[32][DAMAX];
    __shared__ int s_red[32];
    __shared__ int s_dstar, s_r;
    const int tid = threadIdx.x, bid = blockIdx.x, nb = gridDim.x;
    const int gsz = nb * 1024;
    const int g0 = bid * 1024 + tid;
    const int lane = tid & 31, w = tid >> 5;
    const int warpId = g0 >> 5, nwarps = nb * 32;
    const int warpId1 = ((bid - 1) * 1024 + tid) >> 5, nwarps1 = (nb - 1) * 32;
    int ep = 0;

    // ---- ph0: init ----
    for (int i = g0; i < NS; i += gsz) {
        g_srcHist[i] = 0; g_tgtHist[i] = 0; g_histTri[i] = 0; g_deg2[i] = 0;
        g_keptOut[i] = 0; g_keptInK[i] = 0; g_cntKept[i] = 0;
        g_srcPresent[i] = 0; g_present[i] = 0; g_curA[i] = 0;
    }
    for (int i = g0; i < DHIST; i += gsz) g_histD[i] = 0;
    for (int i = g0; i < 12288; i += gsz) {
        int o = i & 63, ii = (i >> 6) & 63, k = i >> 12;
        g_Wt[i] = W[o * 192 + ii * 3 + k];
    }
    if (g0 == 0) g_maxNode = -1;
    gridBar(++ep, nb);

    // ---- ph1: edge histograms ----
    for (int e = g0; e < E; e += gsz) {
        atomicAdd(&g_srcHist[ei[e]], 1);
        atomicAdd(&g_tgtHist[ei[E + e]], 1);
    }
    gridBar(++ep, nb);

    // ---- ph2: b0: scan srcBase.  others: warm x into L2 ----
    if (bid == 0) {
        sbScanFast<5>(g_srcHist, g_srcBase, N);
    } else {
        float acc = 0.f;
        int n4 = N * 16;
        for (int i = (bid - 1) * 1024 + tid; i < n4; i += (nb - 1) * 1024)
            acc += ((const float4*)x)[i].x;
        if (acc == 1.2345e-30f) g_sinkf = acc;
    }
    gridBar(++ep, nb);

    // ---- ph3: scatter by src + analytic degree partials + maxNode ----
    {
        int mloc = -1;
        for (int e = g0; e < E; e += gsz) {
            int s = ei[e], t = ei[E + e];
            g_eScat[g_srcBase[s] + atomicAdd(&g_curA[s], 1)] = e;
            int oh = g_srcHist[t], ih = g_tgtHist[s];
            atomicAdd(&g_histTri[s], oh);
            atomicAdd(&g_deg2[t], ih);
            if (oh > 0 || ih > 0) {
                int mx = s > t ? s : t;
                if (mx > mloc) mloc = mx;
            }
        }
#pragma unroll
        for (int o = 16; o; o >>= 1) {
            int u = __shfl_down_sync(0xffffffffu, mloc, o);
            if (u > mloc) mloc = u;
        }
        if (lane == 0) s_red[w] = mloc;
        __syncthreads();
        if (tid < 32) {
            int m = s_red[tid];
#pragma unroll
            for (int o = 16; o; o >>= 1) {
                int u = __shfl_down_sync(0xffffffffu, m, o);
                if (u > m) m = u;
            }
            if (tid == 0 && m >= 0) atomicMax(&g_maxNode, m);
        }
        __syncthreads();
    }
    gridBar(++ep, nb);

    // ---- ph4: deg finalize + degree histogram (maxNode known) ----
    {
        int L = g_maxNode + 1;
        for (int i = g0; i < NS; i += gsz) {
            int d = g_histTri[i] + g_srcHist[i] * g_tgtHist[i] + g_deg2[i];
            g_deg[i] = d;
            if (i < L) {
                int dd = d > DHIST - 1 ? DHIST - 1 : d;
                atomicAdd(&g_histD[dd], 1);
            }
        }
    }
    gridBar(++ep, nb);

    // ---- ph5: b0: median select + keep.  others: src-bucket stable sort ----
    if (bid == 0) {
        sbScanFast<4>(g_histD, g_cumD, DHIST);
        __syncthreads();
        int L = g_maxNode + 1, half = L >> 1;
        for (int d = tid; d < DHIST; d += 1024)
            if (g_cumD[d] <= half && half < g_cumD[d + 1]) { s_dstar = d; s_r = half - g_cumD[d]; }
        __syncthreads();
        int dstar = s_dstar, r = s_r;
        for (int i = tid; i < NS; i += 1024)
            g_prod[i] = (i < L && g_deg[i] == dstar) ? 1 : 0;
        __syncthreads();
        sbScanFast<5>(g_prod, g_tieEx, N);
        __syncthreads();
        for (int i = tid; i < N; i += 1024) {
            int kp = 1;
            if (i < L) {
                int d = g_deg[i];
                if (d < dstar) kp = 0;
                else if (d == dstar && g_tieEx[i] < r) kp = 0;
            }
            g_keep[i] = kp;
        }
    } else {
        for (int v = warpId1; v < N; v += nwarps1) {
            int lo = g_srcBase[v], s = g_srcBase[v + 1] - lo;
            for (int i = lane; i < s; i += 32) {
                int val = g_eScat[lo + i], r = 0;
                for (int j = 0; j < s; j++) r += (g_eScat[lo + j] < val);
                g_ePerm[lo + r] = val;
            }
            __syncwarp();
            for (int i = lane; i < s; i += 32)
                g_tgtS[lo + i] = ei[E + g_ePerm[lo + i]];
            __syncwarp();
        }
    }
    gridBar(++ep, nb);

    // ---- ph6: kept in/out edge counts ----
    for (int e = g0; e < E; e += gsz) {
        int s = ei[e], t = ei[E + e];
        if (g_keep[t]) atomicAdd(&g_keptOut[s], 1);
        if (g_keep[s]) atomicAdd(&g_keptInK[t], 1);
    }
    gridBar(++ep, nb);

    // ---- ph7: analytic kept-count per bucket + present flags ----
    for (int e = g0; e < E; e += gsz) {
        int s = ei[e], t = ei[E + e];
        if (g_keep[s] && g_keep[t]) {
            int ko = g_keptOut[t];
            if (ko) {
                atomicAdd(&g_cntKept[s], ko);
                g_present[s] = 1;
                g_srcPresent[s] = 1;
            }
            if (g_keptInK[s]) g_present[t] = 1;
        }
    }
    for (int i = g0; i < N; i += gsz)
        if (g_keep[i] && g_keptOut[i] && g_keptInK[i]) g_present[i] = 1;
    gridBar(++ep, nb);

    // ---- ph8: three scans on three blocks in parallel ----
    if (bid == 0) sbScanFast<5>(g_cntKept, g_kBase, N);
    else if (bid == 1) sbScanFast<5>(g_srcPresent, g_srcRank, N);
    else if (bid == 2) sbScanFast<5>(g_present, g_rank, N);
    gridBar(++ep, nb);

    // ---- ph9: direct COMPACTED sorted generation of kept triplets ----
    for (int a = warpId; a < N; a += nwarps) {
        if (!g_keep[a]) continue;
        if (!g_cntKept[a]) continue;
        int lo = g_srcBase[a], da = g_srcBase[a + 1] - lo;
        int dc = da > DAMAX ? DAMAX : da;
        for (int i = lane; i < dc; i += 32) s_uns[w][i] = g_tgtS[lo + i];
        __syncwarp();
        for (int i = lane; i < dc; i += 32) {
            int vi = s_uns[w][i], r = 0;
            for (int j = 0; j < dc; j++) {
                int vj = s_uns[w][j];
                r += (vj < vi) | ((vj == vi) & (j < i));
            }
            s_srt[w][r] = vi;
        }
        __syncwarp();
        for (int i = lane; i < dc; i += 32) {
            int v = s_srt[w][i];
            int eb = g_srcBase[v];
            s_eb[w][i] = eb;
            s_dn[w][i] = g_srcBase[v + 1] - eb;
            s_kv[w][i] = g_keep[v];
        }
        __syncwarp();
        int p = g_kBase[a];
        int idx = 0;
        while (idx < dc) {
            int v = s_srt[w][idx];
            int k = 1;
            while (idx + k < dc && s_srt[w][idx + k] == v) k++;
            if (s_kv[w][idx]) {
                int eb = s_eb[w][idx], din = s_dn[w][idx];
                unsigned vhi = (unsigned)v << 16;
                for (int c0 = 0; c0 < din; c0 += 32) {
                    int rem = din - c0; if (rem > 32) rem = 32;
                    int wv = 0, kp = 0;
                    if (lane < rem) {
                        wv = g_tgtS[eb + c0 + lane];
                        kp = g_keep[wv];
                    }
                    unsigned mask = __ballot_sync(0xffffffffu, kp);
                    int j = __popc(mask & ((1u << lane) - 1u));
                    if (kp) {
                        unsigned val = vhi | (unsigned)wv;
                        for (int c = 0; c < k; c++) g_cVW[p + j * k + c] = val;
                    }
                    p += k * __popc(mask);
                }
            }
            idx += k;
        }
        __syncwarp();
    }
    gridBar(++ep, nb);

    // ---- ph10: fused new_ei output + segment-mean + 3-tap matvec ----
    {
        int U = g_srcRank[N], P = g_kBase[N];
        int obase = 64 * U;
        for (int a = warpId; a < N; a += nwarps) {
            int cnt = g_cntKept[a];
            if (!cnt) continue;
            int u = g_srcRank[a];
            int h0 = g_kBase[a], h1 = h0 + cnt;
            float ra = (float)g_rank[a];
            float2 aB = make_float2(0.f, 0.f), aC = make_float2(0.f, 0.f);
            for (int p0 = h0; p0 < h1; p0 += 32) {
                int rem = h1 - p0; if (rem > 32) rem = 32;
                unsigned vwl = 0;
                if (lane < rem) {
                    vwl = g_cVW[p0 + lane];
                    out[obase + p0 + lane] = ra;
                    out[obase + P + p0 + lane] = (float)g_rank[vwl >> 16];
                    out[obase + 2 * P + p0 + lane] = (float)g_rank[vwl & 0xffffu];
                }
#pragma unroll 8
                for (int j = 0; j < rem; j++) {
                    unsigned vw = __shfl_sync(0xffffffffu, vwl, j);
                    float2 bb = ((const float2*)(x + (vw >> 16) * 64))[lane];
                    float2 cc = ((const float2*)(x + (vw & 0xffffu) * 64))[lane];
                    aB.x += bb.x; aB.y += bb.y;
                    aC.x += cc.x; aC.y += cc.y;
                }
            }
            float inv = 1.0f / (float)cnt;
            float2 xa = ((const float2*)(x + (g_cVW[h0] >> 16) * 0 + a * 64))[lane];
            sv[w][2 * lane] = xa.x;              sv[w][2 * lane + 1] = xa.y;
            sv[w][64 + 2 * lane] = aB.x * inv;   sv[w][64 + 2 * lane + 1] = aB.y * inv;
            sv[w][128 + 2 * lane] = aC.x * inv;  sv[w][128 + 2 * lane + 1] = aC.y * inv;
            __syncwarp();
            float acc0 = bvec[lane], acc1 = bvec[lane + 32];
#pragma unroll 8
            for (int i = 0; i < 64; i++) {
                float v0 = sv[w][i], v1 = sv[w][64 + i], v2 = sv[w][128 + i];
                int base = i * 64 + lane;
                acc0 += g_Wt[base] * v0 + g_Wt[4096 + base] * v1 + g_Wt[8192 + base] * v2;
                acc1 += g_Wt[base + 32] * v0 + g_Wt[4096 + base + 32] * v1 + g_Wt[8192 + base + 32] * v2;
            }
            out[u * 64 + lane] = acc0;
            out[u * 64 + lane + 32] = acc1;
            __syncwarp();
        }
    }
}

extern "C" void kernel_launch(void* const* d_in, const int* in_sizes, int n_in,
                              void* d_out, int out_size) {
    const float* x = (const float*)d_in[0];
    const int* ei = (const int*)d_in[1];
    const float* W = (const float*)d_in[2];
    const float* b = (const float*)d_in[3];
    float* out = (float*)d_out;
    int N = in_sizes[0] / 64;
    int E = in_sizes[1] / 2;

    int dev = 0, sms = 148;
    cudaGetDevice(&dev);
    cudaDeviceGetAttribute(&sms, cudaDevAttrMultiProcessorCount, dev);
    if (sms > MAXB) sms = MAXB;

    kBarInit<<<20, 256>>>();
    kMega<<<sms, 1024>>>(x, ei, W, b, out, N, E);
}

// round 12
// speedup vs baseline: 1.2697x; 1.2697x over previous
#include <cuda_runtime.h>

#define NS 20480
#define EMAX 120000
#define DHIST 4096
#define MAXB 160
#define DAMAX 64

__device__ __align__(16) int g_srcHist[NS + 8], g_tgtHist[NS + 8];
__device__ __align__(16) int g_srcBase[NS + 8];
__device__ int g_curA[NS + 8];
__device__ int g_eScat[EMAX], g_ePerm[EMAX];
__device__ int g_tgtS[EMAX];
__device__ __align__(16) int g_prod[NS + 8];
__device__ __align__(16) int g_histTri[NS + 8];
__device__ __align__(16) int g_deg[NS + 8];
__device__ int g_deg2[NS + 8];
__device__ __align__(16) int g_keptOut[NS + 8], g_keptInK[NS + 8];
__device__ __align__(16) int g_cntKept[NS + 8];
__device__ int g_kBase[NS + 8];
__device__ __align__(16) int g_histD[DHIST + 8];
__device__ int g_cumD[DHIST + 8];
__device__ int g_maxNode, g_cursor;
__device__ float g_sinkf;
__device__ __align__(16) int g_tieEx[NS + 8];
__device__ int g_keep[NS + 8];
__device__ __align__(16) int g_srcPresent[NS + 8], g_present[NS + 8];
__device__ int g_srcRank[NS + 8], g_rank[NS + 8];
__device__ float g_Wt[3 * 64 * 64];
__device__ __align__(16) float g_Sout[NS * 64];   // per-node sum of kept out-neighbor x rows
__device__ volatile int g_arrive[MAXB * 32];
__device__ volatile int g_barPhase;

__device__ __forceinline__ void gridBar(int ep, int nb) {
    __syncthreads();
    if (blockIdx.x == 0) {
        if (threadIdx.x < 32) {
            int lane = threadIdx.x;
            if (lane == 0) { __threadfence(); g_arrive[0] = ep; }
            bool ok;
            do {
                ok = true;
                for (int s = lane; s < nb; s += 32)
                    if (g_arrive[s * 32] < ep) ok = false;
            } while (__ballot_sync(0xffffffffu, !ok));
            if (lane == 0) { __threadfence(); g_barPhase = ep; }
        }
    } else if (threadIdx.x == 0) {
        __threadfence();
        g_arrive[blockIdx.x * 32] = ep;
        while (g_barPhase < ep) __nanosleep(32);
        __threadfence();
    }
    __syncthreads();
}

__device__ __forceinline__ int blockScanEx(int v, int* tot) {
    __shared__ int s_w[32];
    __shared__ int s_tot;
    int lane = threadIdx.x & 31, wid = threadIdx.x >> 5, nw = blockDim.x >> 5;
    int inc = v;
#pragma unroll
    for (int o = 1; o < 32; o <<= 1) {
        int u = __shfl_up_sync(0xffffffffu, inc, o);
        if (lane >= o) inc += u;
    }
    if (lane == 31) s_w[wid] = inc;
    __syncthreads();
    if (wid == 0) {
        int sv2 = (lane < nw) ? s_w[lane] : 0;
        int si = sv2;
#pragma unroll
        for (int o = 1; o < 32; o <<= 1) {
            int u = __shfl_up_sync(0xffffffffu, si, o);
            if (lane >= o) si += u;
        }
        s_w[lane] = si - sv2;
        if (lane == 31) s_tot = si;
    }
    __syncthreads();
    int ex = inc - v + s_w[wid];
    *tot = s_tot;
    __syncthreads();
    return ex;
}

template <int VPT4>
__device__ void sbScanFast(const int* in, int* out, int n) {
    int v[VPT4 * 4];
    const int4* in4 = (const int4*)in;
#pragma unroll
    for (int j = 0; j < VPT4; j++) {
        int4 q = in4[threadIdx.x * VPT4 + j];
        v[4 * j] = q.x; v[4 * j + 1] = q.y; v[4 * j + 2] = q.z; v[4 * j + 3] = q.w;
    }
    int loc = 0;
#pragma unroll
    for (int j = 0; j < VPT4 * 4; j++) { int t = v[j]; v[j] = loc; loc += t; }
    int tot, ex = blockScanEx(loc, &tot);
    int base = threadIdx.x * VPT4 * 4;
#pragma unroll
    for (int j = 0; j < VPT4 * 4; j++) {
        int i = base + j;
        if (i < n) out[i] = ex + v[j];
    }
    if (threadIdx.x == 0) out[n] = tot;
}

__global__ void kBarInit() {
    int i = blockIdx.x * blockDim.x + threadIdx.x;
    if (i < MAXB * 32) g_arrive[i] = 0;
    if (i == 0) g_barPhase = 0;
}

__global__ void __launch_bounds__(1024, 1) kMega(
    const float* __restrict__ x, const int* __restrict__ ei,
    const float* __restrict__ W, const float* __restrict__ bvec,
    float* __restrict__ out, int N, int E)
{
    __shared__ float sv[32][192];
    __shared__ int s_uns[32][DAMAX];
    __shared__ int s_srt[32][DAMAX];
    __shared__ int s_eb[32][DAMAX];
    __shared__ int s_dn[32][DAMAX];
    __shared__ int s_ko[32][DAMAX];
    __shared__ int s_red[32];
    __shared__ int s_dstar, s_r;
    const int tid = threadIdx.x, bid = blockIdx.x, nb = gridDim.x;
    const int gsz = nb * 1024;
    const int g0 = bid * 1024 + tid;
    const int lane = tid & 31, w = tid >> 5;
    const int warpId = g0 >> 5, nwarps = nb * 32;
    const int warpId1 = ((bid - 1) * 1024 + tid) >> 5, nwarps1 = (nb - 1) * 32;
    int ep = 0;

    // ---- ph0: init ----
    for (int i = g0; i < NS; i += gsz) {
        g_srcHist[i] = 0; g_tgtHist[i] = 0; g_histTri[i] = 0; g_deg2[i] = 0;
        g_keptOut[i] = 0; g_keptInK[i] = 0; g_cntKept[i] = 0;
        g_srcPresent[i] = 0; g_present[i] = 0; g_curA[i] = 0;
    }
    for (int i = g0; i < DHIST; i += gsz) g_histD[i] = 0;
    for (int i = g0; i < 12288; i += gsz) {
        int o = i & 63, ii = (i >> 6) & 63, k = i >> 12;
        g_Wt[i] = W[o * 192 + ii * 3 + k];
    }
    if (g0 == 0) { g_maxNode = -1; g_cursor = 0; }
    gridBar(++ep, nb);

    // ---- ph1: edge histograms ----
    for (int e = g0; e < E; e += gsz) {
        atomicAdd(&g_srcHist[ei[e]], 1);
        atomicAdd(&g_tgtHist[ei[E + e]], 1);
    }
    gridBar(++ep, nb);

    // ---- ph2: b0: scan srcBase.  others: warm x into L2 ----
    if (bid == 0) {
        sbScanFast<5>(g_srcHist, g_srcBase, N);
    } else {
        float acc = 0.f;
        int n4 = N * 16;
        for (int i = (bid - 1) * 1024 + tid; i < n4; i += (nb - 1) * 1024)
            acc += ((const float4*)x)[i].x;
        if (acc == 1.2345e-30f) g_sinkf = acc;
    }
    gridBar(++ep, nb);

    // ---- ph3: scatter by src + analytic degree partials + maxNode ----
    {
        int mloc = -1;
        for (int e = g0; e < E; e += gsz) {
            int s = ei[e], t = ei[E + e];
            g_eScat[g_srcBase[s] + atomicAdd(&g_curA[s], 1)] = e;
            int oh = g_srcHist[t], ih = g_tgtHist[s];
            atomicAdd(&g_histTri[s], oh);
            atomicAdd(&g_deg2[t], ih);
            if (oh > 0 || ih > 0) {
                int mx = s > t ? s : t;
                if (mx > mloc) mloc = mx;
            }
        }
#pragma unroll
        for (int o = 16; o; o >>= 1) {
            int u = __shfl_down_sync(0xffffffffu, mloc, o);
            if (u > mloc) mloc = u;
        }
        if (lane == 0) s_red[w] = mloc;
        __syncthreads();
        if (tid < 32) {
            int m = s_red[tid];
#pragma unroll
            for (int o = 16; o; o >>= 1) {
                int u = __shfl_down_sync(0xffffffffu, m, o);
                if (u > m) m = u;
            }
            if (tid == 0 && m >= 0) atomicMax(&g_maxNode, m);
        }
        __syncthreads();
    }
    gridBar(++ep, nb);

    // ---- ph4: deg finalize + degree histogram ----
    {
        int L = g_maxNode + 1;
        for (int i = g0; i < NS; i += gsz) {
            int d = g_histTri[i] + g_srcHist[i] * g_tgtHist[i] + g_deg2[i];
            g_deg[i] = d;
            if (i < L) {
                int dd = d > DHIST - 1 ? DHIST - 1 : d;
                atomicAdd(&g_histD[dd], 1);
            }
        }
    }
    gridBar(++ep, nb);

    // ---- ph5: b0: median select + keep.  others: src-bucket stable sort ----
    if (bid == 0) {
        sbScanFast<1>(g_histD, g_cumD, DHIST);
        __syncthreads();
        int L = g_maxNode + 1, half = L >> 1;
        for (int d = tid; d < DHIST; d += 1024)
            if (g_cumD[d] <= half && half < g_cumD[d + 1]) { s_dstar = d; s_r = half - g_cumD[d]; }
        __syncthreads();
        int dstar = s_dstar, r = s_r;
        for (int i = tid; i < NS; i += 1024)
            g_prod[i] = (i < L && g_deg[i] == dstar) ? 1 : 0;
        __syncthreads();
        sbScanFast<5>(g_prod, g_tieEx, N);
        __syncthreads();
        for (int i = tid; i < N; i += 1024) {
            int kp = 1;
            if (i < L) {
                int d = g_deg[i];
                if (d < dstar) kp = 0;
                else if (d == dstar && g_tieEx[i] < r) kp = 0;
            }
            g_keep[i] = kp;
        }
    } else {
        for (int v = warpId1; v < N; v += nwarps1) {
            int lo = g_srcBase[v], s = g_srcBase[v + 1] - lo;
            for (int i = lane; i < s; i += 32) {
                int val = g_eScat[lo + i], r = 0;
                for (int j = 0; j < s; j++) r += (g_eScat[lo + j] < val);
                g_ePerm[lo + r] = val;
            }
            __syncwarp();
            for (int i = lane; i < s; i += 32)
                g_tgtS[lo + i] = ei[E + g_ePerm[lo + i]];
            __syncwarp();
        }
    }
    gridBar(++ep, nb);

    // ---- ph6: warp-per-kept-node: keptOut + S_out; per-edge keptInK ----
    for (int v = warpId; v < N; v += nwarps) {
        if (!g_keep[v]) continue;
        int lo = g_srcBase[v], s = g_srcBase[v + 1] - lo;
        if (s == 0) continue;
        float2 aS = make_float2(0.f, 0.f);
        int kcnt = 0;
        for (int c0 = 0; c0 < s; c0 += 32) {
            int rem = s - c0; if (rem > 32) rem = 32;
            int wv = 0, kp = 0;
            if (lane < rem) { wv = g_tgtS[lo + c0 + lane]; kp = g_keep[wv]; }
            unsigned mask = __ballot_sync(0xffffffffu, kp);
            kcnt += __popc(mask);
            while (mask) {
                int j = __ffs(mask) - 1; mask &= mask - 1;
                int wvj = __shfl_sync(0xffffffffu, wv, j);
                float2 xx = ((const float2*)(x + wvj * 64))[lane];
                aS.x += xx.x; aS.y += xx.y;
            }
        }
        if (lane == 0) g_keptOut[v] = kcnt;
        ((float2*)(g_Sout + v * 64))[lane] = aS;
    }
    for (int e = g0; e < E; e += gsz) {
        int s = ei[e], t = ei[E + e];
        if (g_keep[s] && g_keep[t]) atomicAdd(&g_keptInK[t], 1);
    }
    gridBar(++ep, nb);

    // ---- ph7: analytic kept-count per bucket + present flags ----
    for (int e = g0; e < E; e += gsz) {
        int s = ei[e], t = ei[E + e];
        if (g_keep[s] && g_keep[t]) {
            int ko = g_keptOut[t];
            if (ko) {
                atomicAdd(&g_cntKept[s], ko);
                g_present[s] = 1;
                g_srcPresent[s] = 1;
            }
            if (g_keptInK[s]) g_present[t] = 1;
        }
    }
    for (int i = g0; i < N; i += gsz)
        if (g_keep[i] && g_keptOut[i] && g_keptInK[i]) g_present[i] = 1;
    gridBar(++ep, nb);

    // ---- ph8: three scans on three blocks in parallel ----
    if (bid == 0) sbScanFast<5>(g_cntKept, g_kBase, N);
    else if (bid == 1) sbScanFast<5>(g_srcPresent, g_srcRank, N);
    else if (bid == 2) sbScanFast<5>(g_present, g_rank, N);
    gridBar(++ep, nb);

    // ---- ph9 (final): fused generation + new_ei + factored segment compute ----
    {
        int U = g_srcRank[N], P = g_kBase[N];
        int obase = 64 * U;
        for (;;) {
            int a;
            if (lane == 0) a = atomicAdd(&g_cursor, 1);
            a = __shfl_sync(0xffffffffu, a, 0);
            if (a >= N) break;
            if (!g_keep[a]) continue;
            int cnt = g_cntKept[a];
            if (!cnt) continue;
            int lo = g_srcBase[a], da = g_srcBase[a + 1] - lo;
            int dc = da > DAMAX ? DAMAX : da;
            for (int i = lane; i < dc; i += 32) s_uns[w][i] = g_tgtS[lo + i];
            __syncwarp();
            for (int i = lane; i < dc; i += 32) {
                int vi = s_uns[w][i], r = 0;
                for (int j = 0; j < dc; j++) {
                    int vj = s_uns[w][j];
                    r += (vj < vi) | ((vj == vi) & (j < i));
                }
                s_srt[w][r] = vi;
            }
            __syncwarp();
            for (int i = lane; i < dc; i += 32) {
                int v = s_srt[w][i];
                int eb = g_srcBase[v];
                s_eb[w][i] = eb;
                s_dn[w][i] = g_srcBase[v + 1] - eb;
                s_ko[w][i] = g_keep[v] ? g_keptOut[v] : 0;
            }
            __syncwarp();
            int u = g_srcRank[a];
            float ra = (float)g_rank[a];
            int p = g_kBase[a];
            float2 aB = make_float2(0.f, 0.f), aC = make_float2(0.f, 0.f);
            int idx = 0;
            while (idx < dc) {
                int v = s_srt[w][idx];
                int k = 1;
                while (idx + k < dc && s_srt[w][idx + k] == v) k++;
                int ko = s_ko[w][idx];
                if (ko) {
                    float kf = (float)k;
                    float m = kf * (float)ko;
                    float2 xv = ((const float2*)(x + v * 64))[lane];
                    float2 so = ((const float2*)(g_Sout + v * 64))[lane];
                    aB.x += m * xv.x; aB.y += m * xv.y;
                    aC.x += kf * so.x; aC.y += kf * so.y;
                    int eb = s_eb[w][idx], din = s_dn[w][idx];
                    float rv = (float)g_rank[v];
                    for (int c0 = 0; c0 < din; c0 += 32) {
                        int rem = din - c0; if (rem > 32) rem = 32;
                        int wv = 0, kp = 0;
                        if (lane < rem) { wv = g_tgtS[eb + c0 + lane]; kp = g_keep[wv]; }
                        unsigned mask = __ballot_sync(0xffffffffu, kp);
                        int j = __popc(mask & ((1u << lane) - 1u));
                        if (kp) {
                            float rw = (float)g_rank[wv];
                            for (int c = 0; c < k; c++) {
                                int pp = p + j * k + c;
                                out[obase + pp] = ra;
                                out[obase + P + pp] = rv;
                                out[obase + 2 * P + pp] = rw;
                            }
                        }
                        p += k * __popc(mask);
                    }
                }
                idx += k;
            }
            float inv = 1.0f / (float)cnt;
            float2 xa = ((const float2*)(x + a * 64))[lane];
            sv[w][2 * lane] = xa.x;              sv[w][2 * lane + 1] = xa.y;
            sv[w][64 + 2 * lane] = aB.x * inv;   sv[w][64 + 2 * lane + 1] = aB.y * inv;
            sv[w][128 + 2 * lane] = aC.x * inv;  sv[w][128 + 2 * lane + 1] = aC.y * inv;
            __syncwarp();
            float acc0 = bvec[lane], acc1 = bvec[lane + 32];
#pragma unroll 8
            for (int i = 0; i < 64; i++) {
                float v0 = sv[w][i], v1 = sv[w][64 + i], v2 = sv[w][128 + i];
                int base = i * 64 + lane;
                acc0 += g_Wt[base] * v0 + g_Wt[4096 + base] * v1 + g_Wt[8192 + base] * v2;
                acc1 += g_Wt[base + 32] * v0 + g_Wt[4096 + base + 32] * v1 + g_Wt[8192 + base + 32] * v2;
            }
            out[u * 64 + lane] = acc0;
            out[u * 64 + lane + 32] = acc1;
            __syncwarp();
        }
    }
}

extern "C" void kernel_launch(void* const* d_in, const int* in_sizes, int n_in,
                              void* d_out, int out_size) {
    const float* x = (const float*)d_in[0];
    const int* ei = (const int*)d_in[1];
    const float* W = (const float*)d_in[2];
    const float* b = (const float*)d_in[3];
    float* out = (float*)d_out;
    int N = in_sizes[0] / 64;
    int E = in_sizes[1] / 2;

    int dev = 0, sms = 148;
    cudaGetDevice(&dev);
    cudaDeviceGetAttribute(&sms, cudaDevAttrMultiProcessorCount, dev);
    if (sms > MAXB) sms = MAXB;

    kBarInit<<<20, 256>>>();
    kMega<<<sms, 1024>>>(x, ei, W, b, out, N, E);
}

// round 13
// speedup vs baseline: 1.4058x; 1.1072x over previous
#include <cuda_runtime.h>

#define NS 20480
#define EMAX 120000
#define DHIST 4096
#define MAXB 160
#define DAMAX 64

__device__ __align__(16) int g_srcHist[NS + 8], g_tgtHist[NS + 8];
__device__ int g_curA[NS + 8];
__device__ __align__(16) int g_eScat[NS * DAMAX];   // stride-64 buckets of edge ids
__device__ __align__(16) int g_tgtS[NS * DAMAX];    // stride-64 buckets of sorted targets
__device__ __align__(16) int g_prod[NS + 8];
__device__ __align__(16) int g_histTri[NS + 8];
__device__ __align__(16) int g_deg[NS + 8];
__device__ int g_deg2[NS + 8];
__device__ __align__(16) int g_keptOut[NS + 8], g_keptInK[NS + 8];
__device__ __align__(16) int g_cntKept[NS + 8];
__device__ int g_kBase[NS + 8];
__device__ __align__(16) int g_histD[DHIST + 8];
__device__ int g_cumD[DHIST + 8];
__device__ int g_maxNode, g_cursor;
__device__ __align__(16) int g_tieEx[NS + 8];
__device__ int g_keep[NS + 8];
__device__ __align__(16) int g_srcPresent[NS + 8], g_present[NS + 8];
__device__ int g_srcRank[NS + 8], g_rank[NS + 8];
__device__ float g_Wt[3 * 64 * 64];
__device__ __align__(16) float g_Sout[NS * 64];     // per-node sum of kept out-neighbor x rows
__device__ volatile int g_arrive[MAXB * 32];
__device__ volatile int g_barPhase;

__device__ __forceinline__ void gridBar(int ep, int nb) {
    __syncthreads();
    if (blockIdx.x == 0) {
        if (threadIdx.x < 32) {
            int lane = threadIdx.x;
            if (lane == 0) { __threadfence(); g_arrive[0] = ep; }
            bool ok;
            do {
                ok = true;
                for (int s = lane; s < nb; s += 32)
                    if (g_arrive[s * 32] < ep) ok = false;
            } while (__ballot_sync(0xffffffffu, !ok));
            if (lane == 0) { __threadfence(); g_barPhase = ep; }
        }
    } else if (threadIdx.x == 0) {
        __threadfence();
        g_arrive[blockIdx.x * 32] = ep;
        while (g_barPhase < ep) __nanosleep(32);
        __threadfence();
    }
    __syncthreads();
}

__device__ __forceinline__ int blockScanEx(int v, int* tot) {
    __shared__ int s_w[32];
    __shared__ int s_tot;
    int lane = threadIdx.x & 31, wid = threadIdx.x >> 5, nw = blockDim.x >> 5;
    int inc = v;
#pragma unroll
    for (int o = 1; o < 32; o <<= 1) {
        int u = __shfl_up_sync(0xffffffffu, inc, o);
        if (lane >= o) inc += u;
    }
    if (lane == 31) s_w[wid] = inc;
    __syncthreads();
    if (wid == 0) {
        int sv2 = (lane < nw) ? s_w[lane] : 0;
        int si = sv2;
#pragma unroll
        for (int o = 1; o < 32; o <<= 1) {
            int u = __shfl_up_sync(0xffffffffu, si, o);
            if (lane >= o) si += u;
        }
        s_w[lane] = si - sv2;
        if (lane == 31) s_tot = si;
    }
    __syncthreads();
    int ex = inc - v + s_w[wid];
    *tot = s_tot;
    __syncthreads();
    return ex;
}

template <int VPT4>
__device__ void sbScanFast(const int* in, int* out, int n) {
    int v[VPT4 * 4];
    const int4* in4 = (const int4*)in;
#pragma unroll
    for (int j = 0; j < VPT4; j++) {
        int4 q = in4[threadIdx.x * VPT4 + j];
        v[4 * j] = q.x; v[4 * j + 1] = q.y; v[4 * j + 2] = q.z; v[4 * j + 3] = q.w;
    }
    int loc = 0;
#pragma unroll
    for (int j = 0; j < VPT4 * 4; j++) { int t = v[j]; v[j] = loc; loc += t; }
    int tot, ex = blockScanEx(loc, &tot);
    int base = threadIdx.x * VPT4 * 4;
#pragma unroll
    for (int j = 0; j < VPT4 * 4; j++) {
        int i = base + j;
        if (i < n) out[i] = ex + v[j];
    }
    if (threadIdx.x == 0) out[n] = tot;
}

// init kernel: barrier state + all zeroing + Wt transpose (off kMega's path)
__global__ void kInitAll(const float* __restrict__ W) {
    int i = blockIdx.x * blockDim.x + threadIdx.x;
    int gsz = gridDim.x * blockDim.x;
    for (int j = i; j < MAXB * 32; j += gsz) g_arrive[j] = 0;
    for (int j = i; j < NS; j += gsz) {
        g_srcHist[j] = 0; g_tgtHist[j] = 0; g_curA[j] = 0;
        g_histTri[j] = 0; g_deg2[j] = 0;
        g_keptOut[j] = 0; g_keptInK[j] = 0; g_cntKept[j] = 0;
        g_srcPresent[j] = 0; g_present[j] = 0;
    }
    for (int j = i; j < DHIST; j += gsz) g_histD[j] = 0;
    for (int j = i; j < 12288; j += gsz) {
        int o = j & 63, ii = (j >> 6) & 63, k = j >> 12;
        g_Wt[j] = W[o * 192 + ii * 3 + k];
    }
    if (i == 0) { g_barPhase = 0; g_maxNode = -1; g_cursor = 0; }
}

__global__ void __launch_bounds__(1024, 1) kMega(
    const float* __restrict__ x, const int* __restrict__ ei,
    const float* __restrict__ bvec, float* __restrict__ out, int N, int E)
{
    __shared__ float sv[32][192];
    __shared__ int s_uns[32][DAMAX];
    __shared__ int s_srt[32][DAMAX];
    __shared__ int s_dn[32][DAMAX];
    __shared__ int s_ko[32][DAMAX];
    __shared__ int s_red[32];
    __shared__ int s_dstar, s_r;
    const int tid = threadIdx.x, bid = blockIdx.x, nb = gridDim.x;
    const int gsz = nb * 1024;
    const int g0 = bid * 1024 + tid;
    const int lane = tid & 31, w = tid >> 5;
    const int warpId = g0 >> 5, nwarps = nb * 32;
    const int warpId1 = ((bid - 1) * 1024 + tid) >> 5, nwarps1 = (nb - 1) * 32;
    int ep = 0;

    // ---- ph1: edge histograms + stride-bucket scatter (no prefix sum needed) ----
    for (int e = g0; e < E; e += gsz) {
        int s = ei[e], t = ei[E + e];
        atomicAdd(&g_srcHist[s], 1);
        atomicAdd(&g_tgtHist[t], 1);
        int slot = atomicAdd(&g_curA[s], 1);
        if (slot < DAMAX) g_eScat[s * DAMAX + slot] = e;
    }
    gridBar(++ep, nb);

    // ---- ph2: analytic degree partials + maxNode ----
    {
        int mloc = -1;
        for (int e = g0; e < E; e += gsz) {
            int s = ei[e], t = ei[E + e];
            int oh = g_srcHist[t], ih = g_tgtHist[s];
            atomicAdd(&g_histTri[s], oh);
            atomicAdd(&g_deg2[t], ih);
            if (oh > 0 || ih > 0) {
                int mx = s > t ? s : t;
                if (mx > mloc) mloc = mx;
            }
        }
#pragma unroll
        for (int o = 16; o; o >>= 1) {
            int u = __shfl_down_sync(0xffffffffu, mloc, o);
            if (u > mloc) mloc = u;
        }
        if (lane == 0) s_red[w] = mloc;
        __syncthreads();
        if (tid < 32) {
            int m = s_red[tid];
#pragma unroll
            for (int o = 16; o; o >>= 1) {
                int u = __shfl_down_sync(0xffffffffu, m, o);
                if (u > m) m = u;
            }
            if (tid == 0 && m >= 0) atomicMax(&g_maxNode, m);
        }
        __syncthreads();
    }
    gridBar(++ep, nb);

    // ---- ph3: deg finalize + degree histogram ----
    {
        int L = g_maxNode + 1;
        for (int i = g0; i < NS; i += gsz) {
            int d = g_histTri[i] + g_srcHist[i] * g_tgtHist[i] + g_deg2[i];
            g_deg[i] = d;
            if (i < L) {
                int dd = d > DHIST - 1 ? DHIST - 1 : d;
                atomicAdd(&g_histD[dd], 1);
            }
        }
    }
    gridBar(++ep, nb);

    // ---- ph4: b0: median select + keep.  others: bucket stable sort ----
    if (bid == 0) {
        sbScanFast<1>(g_histD, g_cumD, DHIST);
        __syncthreads();
        int L = g_maxNode + 1, half = L >> 1;
        for (int d = tid; d < DHIST; d += 1024)
            if (g_cumD[d] <= half && half < g_cumD[d + 1]) { s_dstar = d; s_r = half - g_cumD[d]; }
        __syncthreads();
        int dstar = s_dstar, r = s_r;
        for (int i = tid; i < NS; i += 1024)
            g_prod[i] = (i < L && g_deg[i] == dstar) ? 1 : 0;
        __syncthreads();
        sbScanFast<5>(g_prod, g_tieEx, N);
        __syncthreads();
        for (int i = tid; i < N; i += 1024) {
            int kp = 1;
            if (i < L) {
                int d = g_deg[i];
                if (d < dstar) kp = 0;
                else if (d == dstar && g_tieEx[i] < r) kp = 0;
            }
            g_keep[i] = kp;
        }
    } else {
        for (int v = warpId1; v < N; v += nwarps1) {
            int s = g_srcHist[v];
            int dc = s > DAMAX ? DAMAX : s;
            int lo = v * DAMAX;
            for (int i = lane; i < dc; i += 32) {
                int val = g_eScat[lo + i], r = 0;
                for (int j = 0; j < dc; j++) r += (g_eScat[lo + j] < val);
                g_tgtS[lo + r] = ei[E + val];
            }
            __syncwarp();
        }
    }
    gridBar(++ep, nb);

    // ---- ph5: warp-per-kept-node: keptOut + S_out; per-edge keptInK ----
    for (int v = warpId; v < N; v += nwarps) {
        if (!g_keep[v]) continue;
        int s = g_srcHist[v];
        int dc = s > DAMAX ? DAMAX : s;
        if (dc == 0) continue;
        int lo = v * DAMAX;
        float2 aS = make_float2(0.f, 0.f);
        int kcnt = 0;
        for (int c0 = 0; c0 < dc; c0 += 32) {
            int rem = dc - c0; if (rem > 32) rem = 32;
            int wv = 0, kp = 0;
            if (lane < rem) { wv = g_tgtS[lo + c0 + lane]; kp = g_keep[wv]; }
            unsigned mask = __ballot_sync(0xffffffffu, kp);
            kcnt += __popc(mask);
            while (mask) {
                int j = __ffs(mask) - 1; mask &= mask - 1;
                int wvj = __shfl_sync(0xffffffffu, wv, j);
                float2 xx = ((const float2*)(x + wvj * 64))[lane];
                aS.x += xx.x; aS.y += xx.y;
            }
        }
        if (lane == 0) g_keptOut[v] = kcnt;
        ((float2*)(g_Sout + v * 64))[lane] = aS;
    }
    for (int e = g0; e < E; e += gsz) {
        int s = ei[e], t = ei[E + e];
        if (g_keep[s] && g_keep[t]) atomicAdd(&g_keptInK[t], 1);
    }
    gridBar(++ep, nb);

    // ---- ph6: analytic kept-count per bucket + present flags ----
    for (int e = g0; e < E; e += gsz) {
        int s = ei[e], t = ei[E + e];
        if (g_keep[s] && g_keep[t]) {
            int ko = g_keptOut[t];
            if (ko) {
                atomicAdd(&g_cntKept[s], ko);
                g_present[s] = 1;
                g_srcPresent[s] = 1;
            }
            if (g_keptInK[s]) g_present[t] = 1;
        }
    }
    for (int i = g0; i < N; i += gsz)
        if (g_keep[i] && g_keptOut[i] && g_keptInK[i]) g_present[i] = 1;
    gridBar(++ep, nb);

    // ---- ph7: three scans on three blocks in parallel ----
    if (bid == 0) sbScanFast<5>(g_cntKept, g_kBase, N);
    else if (bid == 1) sbScanFast<5>(g_srcPresent, g_srcRank, N);
    else if (bid == 2) sbScanFast<5>(g_present, g_rank, N);
    gridBar(++ep, nb);

    // ---- ph8 (final): fused generation + new_ei + factored segment compute ----
    {
        int U = g_srcRank[N], P = g_kBase[N];
        int obase = 64 * U;
        for (;;) {
            int base;
            if (lane == 0) base = atomicAdd(&g_cursor, 2);
            base = __shfl_sync(0xffffffffu, base, 0);
            if (base >= N) break;
            for (int a = base; a < base + 2 && a < N; a++) {
                int cnt = g_cntKept[a];
                if (!cnt) continue;
                int da = g_srcHist[a];
                int dc = da > DAMAX ? DAMAX : da;
                int lo = a * DAMAX;
                for (int i = lane; i < dc; i += 32) s_uns[w][i] = g_tgtS[lo + i];
                __syncwarp();
                for (int i = lane; i < dc; i += 32) {
                    int vi = s_uns[w][i], r = 0;
                    for (int j = 0; j < dc; j++) {
                        int vj = s_uns[w][j];
                        r += (vj < vi) | ((vj == vi) & (j < i));
                    }
                    s_srt[w][r] = vi;
                }
                __syncwarp();
                for (int i = lane; i < dc; i += 32) {
                    int v = s_srt[w][i];
                    int dn = g_srcHist[v];
                    s_dn[w][i] = dn > DAMAX ? DAMAX : dn;
                    s_ko[w][i] = g_keep[v] ? g_keptOut[v] : 0;
                }
                __syncwarp();
                int u = g_srcRank[a];
                float ra = (float)g_rank[a];
                int p = g_kBase[a];
                float2 aB = make_float2(0.f, 0.f), aC = make_float2(0.f, 0.f);
                int idx = 0;
                while (idx < dc) {
                    int v = s_srt[w][idx];
                    int k = 1;
                    while (idx + k < dc && s_srt[w][idx + k] == v) k++;
                    int ko = s_ko[w][idx];
                    if (ko) {
                        float kf = (float)k;
                        float m = kf * (float)ko;
                        float2 xv = ((const float2*)(x + v * 64))[lane];
                        float2 so = ((const float2*)(g_Sout + v * 64))[lane];
                        aB.x += m * xv.x; aB.y += m * xv.y;
                        aC.x += kf * so.x; aC.y += kf * so.y;
                        int eb = v * DAMAX, din = s_dn[w][idx];
                        float rv = (float)g_rank[v];
                        for (int c0 = 0; c0 < din; c0 += 32) {
                            int rem = din - c0; if (rem > 32) rem = 32;
                            int wv = 0, kp = 0;
                            if (lane < rem) { wv = g_tgtS[eb + c0 + lane]; kp = g_keep[wv]; }
                            unsigned mask = __ballot_sync(0xffffffffu, kp);
                            int j = __popc(mask & ((1u << lane) - 1u));
                            if (kp) {
                                float rw = (float)g_rank[wv];
                                for (int c = 0; c < k; c++) {
                                    int pp = p + j * k + c;
                                    out[obase + pp] = ra;
                                    out[obase + P + pp] = rv;
                                    out[obase + 2 * P + pp] = rw;
                                }
                            }
                            p += k * __popc(mask);
                        }
                    }
                    idx += k;
                }
                float inv = 1.0f / (float)cnt;
                float2 xa = ((const float2*)(x + a * 64))[lane];
                sv[w][2 * lane] = xa.x;              sv[w][2 * lane + 1] = xa.y;
                sv[w][64 + 2 * lane] = aB.x * inv;   sv[w][64 + 2 * lane + 1] = aB.y * inv;
                sv[w][128 + 2 * lane] = aC.x * inv;  sv[w][128 + 2 * lane + 1] = aC.y * inv;
                __syncwarp();
                float acc0 = bvec[lane], acc1 = bvec[lane + 32];
#pragma unroll 8
                for (int i = 0; i < 64; i++) {
                    float v0 = sv[w][i], v1 = sv[w][64 + i], v2 = sv[w][128 + i];
                    int bb = i * 64 + lane;
                    acc0 += g_Wt[bb] * v0 + g_Wt[4096 + bb] * v1 + g_Wt[8192 + bb] * v2;
                    acc1 += g_Wt[bb + 32] * v0 + g_Wt[4096 + bb + 32] * v1 + g_Wt[8192 + bb + 32] * v2;
                }
                out[u * 64 + lane] = acc0;
                out[u * 64 + lane + 32] = acc1;
                __syncwarp();
            }
        }
    }
}

extern "C" void kernel_launch(void* const* d_in, const int* in_sizes, int n_in,
                              void* d_out, int out_size) {
    const float* x = (const float*)d_in[0];
    const int* ei = (const int*)d_in[1];
    const float* W = (const float*)d_in[2];
    const float* b = (const float*)d_in[3];
    float* out = (float*)d_out;
    int N = in_sizes[0] / 64;
    int E = in_sizes[1] / 2;

    int dev = 0, sms = 148;
    cudaGetDevice(&dev);
    cudaDeviceGetAttribute(&sms, cudaDevAttrMultiProcessorCount, dev);
    if (sms > MAXB) sms = MAXB;

    kInitAll<<<64, 256>>>(W);
    kMega<<<sms, 1024>>>(x, ei, b, out, N, E);
}

// round 14
// speedup vs baseline: 1.4529x; 1.0335x over previous
#include <cuda_runtime.h>

#define NS 20480
#define EMAX 120000
#define DHIST 4096
#define MAXB 160
#define DAMAX 64

__device__ __align__(16) int g_srcHist[NS + 8], g_tgtHist[NS + 8];
__device__ int g_curA[NS + 8];
__device__ __align__(16) int g_eScat[NS * DAMAX];   // stride-64 buckets: edge ids (unsorted)
__device__ __align__(16) int g_tgtU[NS * DAMAX];    // stride-64 buckets: targets (unsorted)
__device__ __align__(16) int g_tgtS[NS * DAMAX];    // stride-64 buckets: targets (sorted by edge id)
__device__ __align__(16) int g_prod[NS + 8];
__device__ __align__(16) int g_histTri[NS + 8];
__device__ __align__(16) int g_deg[NS + 8];
__device__ int g_deg2[NS + 8];
__device__ __align__(16) int g_keptOut[NS + 8], g_keptInK[NS + 8];
__device__ __align__(16) int g_cntKept[NS + 8];
__device__ int g_kBase[NS + 8];
__device__ __align__(16) int g_histD[DHIST + 8];
__device__ int g_cumD[DHIST + 8];
__device__ int g_maxNode, g_cursor;
__device__ __align__(16) int g_tieEx[NS + 8];
__device__ int g_keep[NS + 8];
__device__ __align__(16) int g_srcPresent[NS + 8], g_present[NS + 8];
__device__ int g_srcRank[NS + 8], g_rank[NS + 8];
__device__ float g_Wt[3 * 64 * 64];
__device__ __align__(16) float g_Sout[NS * 64];     // per-node sum of kept out-neighbor x rows
__device__ volatile int g_arrive[MAXB * 32];
__device__ volatile int g_barPhase;

__device__ __forceinline__ void gridBar(int ep, int nb) {
    __syncthreads();
    if (blockIdx.x == 0) {
        if (threadIdx.x < 32) {
            int lane = threadIdx.x;
            if (lane == 0) { __threadfence(); g_arrive[0] = ep; }
            bool ok;
            do {
                ok = true;
                for (int s = lane; s < nb; s += 32)
                    if (g_arrive[s * 32] < ep) ok = false;
            } while (__ballot_sync(0xffffffffu, !ok));
            if (lane == 0) { __threadfence(); g_barPhase = ep; }
        }
    } else if (threadIdx.x == 0) {
        __threadfence();
        g_arrive[blockIdx.x * 32] = ep;
        while (g_barPhase < ep) __nanosleep(32);
        __threadfence();
    }
    __syncthreads();
}

__device__ __forceinline__ int blockScanEx(int v, int* tot) {
    __shared__ int s_w[32];
    __shared__ int s_tot;
    int lane = threadIdx.x & 31, wid = threadIdx.x >> 5, nw = blockDim.x >> 5;
    int inc = v;
#pragma unroll
    for (int o = 1; o < 32; o <<= 1) {
        int u = __shfl_up_sync(0xffffffffu, inc, o);
        if (lane >= o) inc += u;
    }
    if (lane == 31) s_w[wid] = inc;
    __syncthreads();
    if (wid == 0) {
        int sv2 = (lane < nw) ? s_w[lane] : 0;
        int si = sv2;
#pragma unroll
        for (int o = 1; o < 32; o <<= 1) {
            int u = __shfl_up_sync(0xffffffffu, si, o);
            if (lane >= o) si += u;
        }
        s_w[lane] = si - sv2;
        if (lane == 31) s_tot = si;
    }
    __syncthreads();
    int ex = inc - v + s_w[wid];
    *tot = s_tot;
    __syncthreads();
    return ex;
}

template <int VPT4>
__device__ void sbScanFast(const int* in, int* out, int n) {
    int v[VPT4 * 4];
    const int4* in4 = (const int4*)in;
#pragma unroll
    for (int j = 0; j < VPT4; j++) {
        int4 q = in4[threadIdx.x * VPT4 + j];
        v[4 * j] = q.x; v[4 * j + 1] = q.y; v[4 * j + 2] = q.z; v[4 * j + 3] = q.w;
    }
    int loc = 0;
#pragma unroll
    for (int j = 0; j < VPT4 * 4; j++) { int t = v[j]; v[j] = loc; loc += t; }
    int tot, ex = blockScanEx(loc, &tot);
    int base = threadIdx.x * VPT4 * 4;
#pragma unroll
    for (int j = 0; j < VPT4 * 4; j++) {
        int i = base + j;
        if (i < n) out[i] = ex + v[j];
    }
    if (threadIdx.x == 0) out[n] = tot;
}

__global__ void kInitAll(const float* __restrict__ W) {
    int i = blockIdx.x * blockDim.x + threadIdx.x;
    int gsz = gridDim.x * blockDim.x;
    for (int j = i; j < MAXB * 32; j += gsz) g_arrive[j] = 0;
    for (int j = i; j < NS; j += gsz) {
        g_srcHist[j] = 0; g_tgtHist[j] = 0; g_curA[j] = 0;
        g_histTri[j] = 0; g_deg2[j] = 0;
        g_keptOut[j] = 0; g_keptInK[j] = 0; g_cntKept[j] = 0;
        g_srcPresent[j] = 0; g_present[j] = 0;
    }
    for (int j = i; j < DHIST; j += gsz) g_histD[j] = 0;
    for (int j = i; j < 12288; j += gsz) {
        int o = j & 63, ii = (j >> 6) & 63, k = j >> 12;
        g_Wt[j] = W[o * 192 + ii * 3 + k];
    }
    if (i == 0) { g_barPhase = 0; g_maxNode = -1; g_cursor = 0; }
}

__global__ void __launch_bounds__(1024, 1) kMega(
    const float* __restrict__ x, const int* __restrict__ ei,
    const float* __restrict__ bvec, float* __restrict__ out, int N, int E)
{
    __shared__ float sv[32][192];
    __shared__ int s_uns[32][DAMAX];
    __shared__ int s_srt[32][DAMAX];
    __shared__ int s_dn[32][DAMAX];
    __shared__ int s_ko[32][DAMAX];
    __shared__ int s_red[32];
    __shared__ int s_dstar, s_r;
    const int tid = threadIdx.x, bid = blockIdx.x, nb = gridDim.x;
    const int gsz = nb * 1024;
    const int g0 = bid * 1024 + tid;
    const int lane = tid & 31, w = tid >> 5;
    const int warpId = g0 >> 5, nwarps = nb * 32;
    const int warpId1 = ((bid - 1) * 1024 + tid) >> 5, nwarps1 = (nb - 1) * 32;
    int ep = 0;

    // ---- ph1: edge histograms + bucket scatter of (edge id, target) ----
    for (int e = g0; e < E; e += gsz) {
        int s = ei[e], t = ei[E + e];
        atomicAdd(&g_srcHist[s], 1);
        atomicAdd(&g_tgtHist[t], 1);
        int slot = atomicAdd(&g_curA[s], 1);
        if (slot < DAMAX) {
            g_eScat[s * DAMAX + slot] = e;
            g_tgtU[s * DAMAX + slot] = t;
        }
    }
    gridBar(++ep, nb);

    // ---- ph2: warp-per-node: histTri (atomic-free) + deg2 scatter atomics ----
    for (int s = warpId; s < N; s += nwarps) {
        int da = g_srcHist[s];
        if (da == 0) continue;
        int dc = da > DAMAX ? DAMAX : da;
        int lo = s * DAMAX;
        int ih = g_tgtHist[s];
        int acc = 0;
        for (int i = lane; i < dc; i += 32) {
            int t = g_tgtU[lo + i];
            acc += g_srcHist[t];
            atomicAdd(&g_deg2[t], ih);
        }
#pragma unroll
        for (int o = 16; o; o >>= 1) acc += __shfl_down_sync(0xffffffffu, acc, o);
        if (lane == 0) g_histTri[s] = acc;
    }
    gridBar(++ep, nb);

    // ---- ph3: deg finalize + full-N degree histogram + maxNode ----
    {
        int mloc = -1;
        for (int i = g0; i < N; i += gsz) {
            int d = g_histTri[i] + g_srcHist[i] * g_tgtHist[i] + g_deg2[i];
            g_deg[i] = d;
            int dd = d > DHIST - 1 ? DHIST - 1 : d;
            atomicAdd(&g_histD[dd], 1);
            if (d > 0 && i > mloc) mloc = i;
        }
#pragma unroll
        for (int o = 16; o; o >>= 1) {
            int u = __shfl_down_sync(0xffffffffu, mloc, o);
            if (u > mloc) mloc = u;
        }
        if (lane == 0) s_red[w] = mloc;
        __syncthreads();
        if (tid < 32) {
            int m = s_red[tid];
#pragma unroll
            for (int o = 16; o; o >>= 1) {
                int u = __shfl_down_sync(0xffffffffu, m, o);
                if (u > m) m = u;
            }
            if (tid == 0 && m >= 0) atomicMax(&g_maxNode, m);
        }
        __syncthreads();
    }
    gridBar(++ep, nb);

    // ---- ph4: b0: median select + keep (with extra-zeros adjust).  others: sort buckets ----
    if (bid == 0) {
        sbScanFast<1>(g_histD, g_cumD, DHIST);
        __syncthreads();
        int L = g_maxNode + 1, half = L >> 1;
        int extra = N - L;                       // deg-0 nodes beyond maxNode
        for (int d = tid; d < DHIST; d += 1024) {
            int lo2 = g_cumD[d] - (d > 0 ? extra : 0);
            int hi2 = g_cumD[d + 1] - extra;
            if (lo2 <= half && half < hi2) { s_dstar = d; s_r = half - lo2; }
        }
        __syncthreads();
        int dstar = s_dstar, r = s_r;
        for (int i = tid; i < NS; i += 1024)
            g_prod[i] = (i < L && g_deg[i] == dstar) ? 1 : 0;
        __syncthreads();
        sbScanFast<5>(g_prod, g_tieEx, N);
        __syncthreads();
        for (int i = tid; i < N; i += 1024) {
            int kp = 1;
            if (i < L) {
                int d = g_deg[i];
                if (d < dstar) kp = 0;
                else if (d == dstar && g_tieEx[i] < r) kp = 0;
            }
            g_keep[i] = kp;
        }
    } else {
        for (int v = warpId1; v < N; v += nwarps1) {
            int s = g_srcHist[v];
            if (s == 0) continue;
            int dc = s > DAMAX ? DAMAX : s;
            int lo = v * DAMAX;
            for (int i = lane; i < dc; i += 32) s_uns[w][i] = g_eScat[lo + i];
            __syncwarp();
            for (int i = lane; i < dc; i += 32) {
                int val = s_uns[w][i], r = 0;
                for (int j = 0; j < dc; j++) r += (s_uns[w][j] < val);
                g_tgtS[lo + r] = g_tgtU[lo + i];
            }
            __syncwarp();
        }
    }
    gridBar(++ep, nb);

    // ---- ph5: warp-per-kept-node: keptOut (ballot, no atomic) + keptInK scatter ----
    for (int s = warpId; s < N; s += nwarps) {
        if (!g_keep[s]) continue;
        int da = g_srcHist[s];
        if (da == 0) continue;
        int dc = da > DAMAX ? DAMAX : da;
        int lo = s * DAMAX;
        int kcnt = 0;
        for (int c0 = 0; c0 < dc; c0 += 32) {
            int rem = dc - c0; if (rem > 32) rem = 32;
            int t = 0, kp = 0;
            if (lane < rem) { t = g_tgtS[lo + c0 + lane]; kp = g_keep[t]; }
            unsigned mask = __ballot_sync(0xffffffffu, kp);
            kcnt += __popc(mask);
            if (kp) atomicAdd(&g_keptInK[t], 1);
        }
        if (lane == 0) g_keptOut[s] = kcnt;
    }
    gridBar(++ep, nb);

    // ---- ph6: warp-per-kept-node: cntKept (reduce, no atomic) + present flags ----
    for (int s = warpId; s < N; s += nwarps) {
        if (!g_keep[s]) continue;
        int da = g_srcHist[s];
        int dc = da > DAMAX ? DAMAX : da;
        int lo = s * DAMAX;
        int cnt = 0;
        int sInK = g_keptInK[s];
        for (int c0 = 0; c0 < dc; c0 += 32) {
            int rem = dc - c0; if (rem > 32) rem = 32;
            int t = 0, kp = 0;
            if (lane < rem) { t = g_tgtS[lo + c0 + lane]; kp = g_keep[t]; }
            if (kp) {
                cnt += g_keptOut[t];
                if (sInK) g_present[t] = 1;     // t's w-role presence
            }
        }
#pragma unroll
        for (int o = 16; o; o >>= 1) cnt += __shfl_down_sync(0xffffffffu, cnt, o);
        cnt = __shfl_sync(0xffffffffu, cnt, 0);
        if (lane == 0) {
            g_cntKept[s] = cnt;
            if (cnt > 0) { g_present[s] = 1; g_srcPresent[s] = 1; }
            if (g_keptOut[s] && sInK) g_present[s] = 1;   // v-role presence
        }
    }
    gridBar(++ep, nb);

    // ---- ph7: three scans on blocks 0-2; blocks 3+: Sout for kept nodes ----
    if (bid == 0) sbScanFast<5>(g_cntKept, g_kBase, N);
    else if (bid == 1) sbScanFast<5>(g_srcPresent, g_srcRank, N);
    else if (bid == 2) sbScanFast<5>(g_present, g_rank, N);
    else {
        int warpId3 = ((bid - 3) * 1024 + tid) >> 5, nwarps3 = (nb - 3) * 32;
        for (int v = warpId3; v < N; v += nwarps3) {
            if (!g_keep[v]) continue;
            int da = g_srcHist[v];
            if (da == 0) continue;
            int dc = da > DAMAX ? DAMAX : da;
            int lo = v * DAMAX;
            float2 aS = make_float2(0.f, 0.f);
            int any = 0;
            for (int c0 = 0; c0 < dc; c0 += 32) {
                int rem = dc - c0; if (rem > 32) rem = 32;
                int wv = 0, kp = 0;
                if (lane < rem) { wv = g_tgtS[lo + c0 + lane]; kp = g_keep[wv]; }
                unsigned mask = __ballot_sync(0xffffffffu, kp);
                any |= mask;
                while (mask) {
                    int j = __ffs(mask) - 1; mask &= mask - 1;
                    int wvj = __shfl_sync(0xffffffffu, wv, j);
                    float2 xx = ((const float2*)(x + wvj * 64))[lane];
                    aS.x += xx.x; aS.y += xx.y;
                }
            }
            if (any) ((float2*)(g_Sout + v * 64))[lane] = aS;
        }
    }
    gridBar(++ep, nb);

    // ---- ph8 (final): fused generation + new_ei + factored segment compute ----
    {
        int U = g_srcRank[N], P = g_kBase[N];
        int obase = 64 * U;
        for (;;) {
            int base;
            if (lane == 0) base = atomicAdd(&g_cursor, 2);
            base = __shfl_sync(0xffffffffu, base, 0);
            if (base >= N) break;
            for (int a = base; a < base + 2 && a < N; a++) {
                int cnt = g_cntKept[a];
                if (!cnt) continue;
                int da = g_srcHist[a];
                int dc = da > DAMAX ? DAMAX : da;
                int lo = a * DAMAX;
                for (int i = lane; i < dc; i += 32) s_uns[w][i] = g_tgtS[lo + i];
                __syncwarp();
                for (int i = lane; i < dc; i += 32) {
                    int vi = s_uns[w][i], r = 0;
                    for (int j = 0; j < dc; j++) {
                        int vj = s_uns[w][j];
                        r += (vj < vi) | ((vj == vi) & (j < i));
                    }
                    s_srt[w][r] = vi;
                }
                __syncwarp();
                for (int i = lane; i < dc; i += 32) {
                    int v = s_srt[w][i];
                    int dn = g_srcHist[v];
                    s_dn[w][i] = dn > DAMAX ? DAMAX : dn;
                    s_ko[w][i] = g_keep[v] ? g_keptOut[v] : 0;
                }
                __syncwarp();
                int u = g_srcRank[a];
                float ra = (float)g_rank[a];
                int p = g_kBase[a];
                float2 aB = make_float2(0.f, 0.f), aC = make_float2(0.f, 0.f);
                int idx = 0;
                while (idx < dc) {
                    int v = s_srt[w][idx];
                    int k = 1;
                    while (idx + k < dc && s_srt[w][idx + k] == v) k++;
                    int ko = s_ko[w][idx];
                    if (ko) {
                        float kf = (float)k;
                        float m = kf * (float)ko;
                        float2 xv = ((const float2*)(x + v * 64))[lane];
                        float2 so = ((const float2*)(g_Sout + v * 64))[lane];
                        aB.x += m * xv.x; aB.y += m * xv.y;
                        aC.x += kf * so.x; aC.y += kf * so.y;
                        int eb = v * DAMAX, din = s_dn[w][idx];
                        float rv = (float)g_rank[v];
                        for (int c0 = 0; c0 < din; c0 += 32) {
                            int rem = din - c0; if (rem > 32) rem = 32;
                            int wv = 0, kp = 0;
                            if (lane < rem) { wv = g_tgtS[eb + c0 + lane]; kp = g_keep[wv]; }
                            unsigned mask = __ballot_sync(0xffffffffu, kp);
                            int j = __popc(mask & ((1u << lane) - 1u));
                            if (kp) {
                                float rw = (float)g_rank[wv];
                                for (int c = 0; c < k; c++) {
                                    int pp = p + j * k + c;
                                    out[obase + pp] = ra;
                                    out[obase + P + pp] = rv;
                                    out[obase + 2 * P + pp] = rw;
                                }
                            }
                            p += k * __popc(mask);
                        }
                    }
                    idx += k;
                }
                float inv = 1.0f / (float)cnt;
                float2 xa = ((const float2*)(x + a * 64))[lane];
                sv[w][2 * lane] = xa.x;              sv[w][2 * lane + 1] = xa.y;
                sv[w][64 + 2 * lane] = aB.x * inv;   sv[w][64 + 2 * lane + 1] = aB.y * inv;
                sv[w][128 + 2 * lane] = aC.x * inv;  sv[w][128 + 2 * lane + 1] = aC.y * inv;
                __syncwarp();
                float acc0 = bvec[lane], acc1 = bvec[lane + 32];
#pragma unroll 8
                for (int i = 0; i < 64; i++) {
                    float v0 = sv[w][i], v1 = sv[w][64 + i], v2 = sv[w][128 + i];
                    int bb = i * 64 + lane;
                    acc0 += g_Wt[bb] * v0 + g_Wt[4096 + bb] * v1 + g_Wt[8192 + bb] * v2;
                    acc1 += g_Wt[bb + 32] * v0 + g_Wt[4096 + bb + 32] * v1 + g_Wt[8192 + bb + 32] * v2;
                }
                out[u * 64 + lane] = acc0;
                out[u * 64 + lane + 32] = acc1;
                __syncwarp();
            }
        }
    }
}

extern "C" void kernel_launch(void* const* d_in, const int* in_sizes, int n_in,
                              void* d_out, int out_size) {
    const float* x = (const float*)d_in[0];
    const int* ei = (const int*)d_in[1];
    const float* W = (const float*)d_in[2];
    const float* b = (const float*)d_in[3];
    float* out = (float*)d_out;
    int N = in_sizes[0] / 64;
    int E = in_sizes[1] / 2;

    int dev = 0, sms = 148;
    cudaGetDevice(&dev);
    cudaDeviceGetAttribute(&sms, cudaDevAttrMultiProcessorCount, dev);
    if (sms > MAXB) sms = MAXB;

    kInitAll<<<64, 256>>>(W);
    kMega<<<sms, 1024>>>(x, ei, b, out, N, E);
}

// round 15
// speedup vs baseline: 1.4716x; 1.0128x over previous
#include <cuda_runtime.h>

#define NS 20480
#define EMAX 120000
#define DHIST 4096
#define MAXB 160
#define DAMAX 64

__device__ __align__(16) int g_tgtHist[NS + 8];
__device__ __align__(16) int g_curA[NS + 8];        // doubles as srcHist after ph1
__device__ __align__(16) int g_eScat[NS * DAMAX];   // stride-64 buckets: edge ids (unsorted)
__device__ __align__(16) int g_tgtU[NS * DAMAX];    // stride-64 buckets: targets (unsorted)
__device__ __align__(16) int g_tgtS[NS * DAMAX];    // stride-64 buckets: targets (sorted by edge id)
__device__ __align__(16) int g_prod[NS + 8];
__device__ __align__(16) int g_histTri[NS + 8];
__device__ __align__(16) int g_deg[NS + 8];
__device__ int g_deg2[NS + 8];
__device__ __align__(16) int g_keptOut[NS + 8], g_keptInK[NS + 8];
__device__ __align__(16) int g_cntKept[NS + 8];
__device__ int g_kBase[NS + 8];
__device__ __align__(16) int g_histD[DHIST + 8];
__device__ int g_cumD[DHIST + 8];
__device__ int g_maxNode, g_cursor;
__device__ __align__(16) int g_tieEx[NS + 8];
__device__ int g_keep[NS + 8];
__device__ __align__(16) int g_srcPresent[NS + 8], g_present[NS + 8];
__device__ int g_srcRank[NS + 8], g_rank[NS + 8];
__device__ float g_Wt[3 * 64 * 64];
__device__ __align__(16) float g_Sout[NS * 64];     // per-node sum of kept out-neighbor x rows
__device__ volatile int g_arrive[MAXB * 32];
__device__ volatile int g_barPhase;
__device__ volatile int g_mini[8];

__device__ __forceinline__ void gridBar(int ep, int nb) {
    __syncthreads();
    if (blockIdx.x == 0) {
        if (threadIdx.x < 32) {
            int lane = threadIdx.x;
            if (lane == 0) { __threadfence(); g_arrive[0] = ep; }
            bool ok;
            do {
                ok = true;
                for (int s = lane; s < nb; s += 32)
                    if (g_arrive[s * 32] < ep) ok = false;
            } while (__ballot_sync(0xffffffffu, !ok));
            if (lane == 0) { __threadfence(); g_barPhase = ep; }
        }
    } else if (threadIdx.x == 0) {
        __threadfence();
        g_arrive[blockIdx.x * 32] = ep;
        while (g_barPhase < ep) __nanosleep(32);
        __threadfence();
    }
    __syncthreads();
}

__device__ __forceinline__ int blockScanEx(int v, int* tot) {
    __shared__ int s_w[32];
    __shared__ int s_tot;
    int lane = threadIdx.x & 31, wid = threadIdx.x >> 5, nw = blockDim.x >> 5;
    int inc = v;
#pragma unroll
    for (int o = 1; o < 32; o <<= 1) {
        int u = __shfl_up_sync(0xffffffffu, inc, o);
        if (lane >= o) inc += u;
    }
    if (lane == 31) s_w[wid] = inc;
    __syncthreads();
    if (wid == 0) {
        int sv2 = (lane < nw) ? s_w[lane] : 0;
        int si = sv2;
#pragma unroll
        for (int o = 1; o < 32; o <<= 1) {
            int u = __shfl_up_sync(0xffffffffu, si, o);
            if (lane >= o) si += u;
        }
        s_w[lane] = si - sv2;
        if (lane == 31) s_tot = si;
    }
    __syncthreads();
    int ex = inc - v + s_w[wid];
    *tot = s_tot;
    __syncthreads();
    return ex;
}

template <int VPT4>
__device__ void sbScanFast(const int* in, int* out, int n) {
    int v[VPT4 * 4];
    const int4* in4 = (const int4*)in;
#pragma unroll
    for (int j = 0; j < VPT4; j++) {
        int4 q = in4[threadIdx.x * VPT4 + j];
        v[4 * j] = q.x; v[4 * j + 1] = q.y; v[4 * j + 2] = q.z; v[4 * j + 3] = q.w;
    }
    int loc = 0;
#pragma unroll
    for (int j = 0; j < VPT4 * 4; j++) { int t = v[j]; v[j] = loc; loc += t; }
    int tot, ex = blockScanEx(loc, &tot);
    int base = threadIdx.x * VPT4 * 4;
#pragma unroll
    for (int j = 0; j < VPT4 * 4; j++) {
        int i = base + j;
        if (i < n) out[i] = ex + v[j];
    }
    if (threadIdx.x == 0) out[n] = tot;
}

__global__ void kInitAll(const float* __restrict__ W) {
    int i = blockIdx.x * blockDim.x + threadIdx.x;
    int gsz = gridDim.x * blockDim.x;
    for (int j = i; j < MAXB * 32; j += gsz) g_arrive[j] = 0;
    for (int j = i; j < NS; j += gsz) {
        g_tgtHist[j] = 0; g_curA[j] = 0;
        g_histTri[j] = 0; g_deg2[j] = 0;
        g_keptOut[j] = 0; g_keptInK[j] = 0; g_cntKept[j] = 0;
        g_srcPresent[j] = 0; g_present[j] = 0;
    }
    for (int j = i; j < DHIST; j += gsz) g_histD[j] = 0;
    for (int j = i; j < 12288; j += gsz) {
        int o = j & 63, ii = (j >> 6) & 63, k = j >> 12;
        g_Wt[j] = W[o * 192 + ii * 3 + k];
    }
    if (i < 8) g_mini[i] = 0;
    if (i == 0) { g_barPhase = 0; g_maxNode = -1; g_cursor = 0; }
}

__global__ void __launch_bounds__(1024, 1) kMega(
    const float* __restrict__ x, const int* __restrict__ ei,
    const float* __restrict__ bvec, float* __restrict__ out, int N, int E)
{
    __shared__ float sv[32][192];
    __shared__ int s_uns[32][DAMAX];
    __shared__ int s_srt[32][DAMAX];
    __shared__ int s_dn[32][DAMAX];
    __shared__ int s_ko[32][DAMAX];
    __shared__ int s_red[32];
    __shared__ int s_dstar, s_r;
    const int tid = threadIdx.x, bid = blockIdx.x, nb = gridDim.x;
    const int gsz = nb * 1024;
    const int g0 = bid * 1024 + tid;
    const int lane = tid & 31, w = tid >> 5;
    const int warpId = g0 >> 5, nwarps = nb * 32;
    int ep = 0;

    // ---- ph1: tgt histogram + bucket scatter (curA slot counter == srcHist) ----
    for (int e = g0; e < E; e += gsz) {
        int s = ei[e], t = ei[E + e];
        atomicAdd(&g_tgtHist[t], 1);
        int slot = atomicAdd(&g_curA[s], 1);
        if (slot < DAMAX) {
            g_eScat[s * DAMAX + slot] = e;
            g_tgtU[s * DAMAX + slot] = t;
        }
    }
    gridBar(++ep, nb);

    // ---- ph2: warp-per-node: histTri (atomic-free) + deg2 scatter atomics ----
    for (int s = warpId; s < N; s += nwarps) {
        int da = g_curA[s];
        if (da == 0) continue;
        int dc = da > DAMAX ? DAMAX : da;
        int lo = s * DAMAX;
        int ih = g_tgtHist[s];
        int acc = 0;
        for (int i = lane; i < dc; i += 32) {
            int t = g_tgtU[lo + i];
            acc += g_curA[t];
            atomicAdd(&g_deg2[t], ih);
        }
#pragma unroll
        for (int o = 16; o; o >>= 1) acc += __shfl_down_sync(0xffffffffu, acc, o);
        if (lane == 0) g_histTri[s] = acc;
    }
    gridBar(++ep, nb);

    // ---- ph3 (merged): blocks 0-7: deg finalize + histD + maxNode (N/8 each);
    //      mini-sync; b0: median chain + keep.  blocks 8+: bucket stable sort ----
    if (bid < 8) {
        int chunk = (N + 7) / 8;
        int lo3 = bid * chunk, hi3 = lo3 + chunk; if (hi3 > N) hi3 = N;
        int mloc = -1;
        for (int i = lo3 + tid; i < hi3; i += 1024) {
            int d = g_histTri[i] + g_curA[i] * g_tgtHist[i] + g_deg2[i];
            g_deg[i] = d;
            int dd = d > DHIST - 1 ? DHIST - 1 : d;
            atomicAdd(&g_histD[dd], 1);
            if (d > 0 && i > mloc) mloc = i;
        }
#pragma unroll
        for (int o = 16; o; o >>= 1) {
            int u = __shfl_down_sync(0xffffffffu, mloc, o);
            if (u > mloc) mloc = u;
        }
        if (lane == 0) s_red[w] = mloc;
        __syncthreads();
        if (tid < 32) {
            int m = s_red[tid];
#pragma unroll
            for (int o = 16; o; o >>= 1) {
                int u = __shfl_down_sync(0xffffffffu, m, o);
                if (u > m) m = u;
            }
            if (tid == 0 && m >= 0) atomicMax(&g_maxNode, m);
        }
        __syncthreads();
        if (tid == 0) { __threadfence(); g_mini[bid] = 1; }
        if (bid == 0) {
            // wait for all 8 partitions
            if (tid == 0) {
                bool ok;
                do {
                    ok = true;
                    for (int s = 0; s < 8; s++) if (g_mini[s] == 0) ok = false;
                } while (!ok);
                __threadfence();
            }
            __syncthreads();
            sbScanFast<1>(g_histD, g_cumD, DHIST);
            __syncthreads();
            int L = g_maxNode + 1, half = L >> 1;
            int extra = N - L;
            for (int d = tid; d < DHIST; d += 1024) {
                int lo2 = g_cumD[d] - (d > 0 ? extra : 0);
                int hi2 = g_cumD[d + 1] - extra;
                if (lo2 <= half && half < hi2) { s_dstar = d; s_r = half - lo2; }
            }
            __syncthreads();
            int dstar = s_dstar, r = s_r;
            for (int i = tid; i < NS; i += 1024)
                g_prod[i] = (i < L && g_deg[i] == dstar) ? 1 : 0;
            __syncthreads();
            sbScanFast<5>(g_prod, g_tieEx, N);
            __syncthreads();
            for (int i = tid; i < N; i += 1024) {
                int kp = 1;
                if (i < L) {
                    int d = g_deg[i];
                    if (d < dstar) kp = 0;
                    else if (d == dstar && g_tieEx[i] < r) kp = 0;
                }
                g_keep[i] = kp;
            }
        }
    } else {
        int warpId8 = ((bid - 8) * 1024 + tid) >> 5, nwarps8 = (nb - 8) * 32;
        for (int v = warpId8; v < N; v += nwarps8) {
            int s = g_curA[v];
            if (s == 0) continue;
            int dc = s > DAMAX ? DAMAX : s;
            int lo = v * DAMAX;
            for (int i = lane; i < dc; i += 32) s_uns[w][i] = g_eScat[lo + i];
            __syncwarp();
            for (int i = lane; i < dc; i += 32) {
                int val = s_uns[w][i], r = 0;
                for (int j = 0; j < dc; j++) r += (s_uns[w][j] < val);
                g_tgtS[lo + r] = g_tgtU[lo + i];
            }
            __syncwarp();
        }
    }
    gridBar(++ep, nb);

    // ---- ph4: warp-per-kept-node: keptOut (ballot) + keptInK scatter ----
    for (int s = warpId; s < N; s += nwarps) {
        if (!g_keep[s]) continue;
        int da = g_curA[s];
        if (da == 0) continue;
        int dc = da > DAMAX ? DAMAX : da;
        int lo = s * DAMAX;
        int kcnt = 0;
        for (int c0 = 0; c0 < dc; c0 += 32) {
            int rem = dc - c0; if (rem > 32) rem = 32;
            int t = 0, kp = 0;
            if (lane < rem) { t = g_tgtS[lo + c0 + lane]; kp = g_keep[t]; }
            unsigned mask = __ballot_sync(0xffffffffu, kp);
            kcnt += __popc(mask);
            if (kp) atomicAdd(&g_keptInK[t], 1);
        }
        if (lane == 0) g_keptOut[s] = kcnt;
    }
    gridBar(++ep, nb);

    // ---- ph5: warp-per-kept-node: cntKept (reduce) + present flags ----
    for (int s = warpId; s < N; s += nwarps) {
        if (!g_keep[s]) continue;
        int da = g_curA[s];
        int dc = da > DAMAX ? DAMAX : da;
        int lo = s * DAMAX;
        int cnt = 0;
        int sInK = g_keptInK[s];
        for (int c0 = 0; c0 < dc; c0 += 32) {
            int rem = dc - c0; if (rem > 32) rem = 32;
            int t = 0, kp = 0;
            if (lane < rem) { t = g_tgtS[lo + c0 + lane]; kp = g_keep[t]; }
            if (kp) {
                cnt += g_keptOut[t];
                if (sInK) g_present[t] = 1;
            }
        }
#pragma unroll
        for (int o = 16; o; o >>= 1) cnt += __shfl_down_sync(0xffffffffu, cnt, o);
        cnt = __shfl_sync(0xffffffffu, cnt, 0);
        if (lane == 0) {
            g_cntKept[s] = cnt;
            if (cnt > 0) { g_present[s] = 1; g_srcPresent[s] = 1; }
            if (g_keptOut[s] && sInK) g_present[s] = 1;
        }
    }
    gridBar(++ep, nb);

    // ---- ph6: three scans on blocks 0-2; blocks 3+: Sout for kept nodes ----
    if (bid == 0) sbScanFast<5>(g_cntKept, g_kBase, N);
    else if (bid == 1) sbScanFast<5>(g_srcPresent, g_srcRank, N);
    else if (bid == 2) sbScanFast<5>(g_present, g_rank, N);
    else {
        int warpId3 = ((bid - 3) * 1024 + tid) >> 5, nwarps3 = (nb - 3) * 32;
        for (int v = warpId3; v < N; v += nwarps3) {
            if (!g_keep[v]) continue;
            int da = g_curA[v];
            if (da == 0) continue;
            int dc = da > DAMAX ? DAMAX : da;
            int lo = v * DAMAX;
            float2 aS = make_float2(0.f, 0.f);
            int any = 0;
            for (int c0 = 0; c0 < dc; c0 += 32) {
                int rem = dc - c0; if (rem > 32) rem = 32;
                int wv = 0, kp = 0;
                if (lane < rem) { wv = g_tgtS[lo + c0 + lane]; kp = g_keep[wv]; }
                unsigned mask = __ballot_sync(0xffffffffu, kp);
                any |= mask;
                while (mask) {
                    int j = __ffs(mask) - 1; mask &= mask - 1;
                    int wvj = __shfl_sync(0xffffffffu, wv, j);
                    float2 xx = ((const float2*)(x + wvj * 64))[lane];
                    aS.x += xx.x; aS.y += xx.y;
                }
            }
            if (any) ((float2*)(g_Sout + v * 64))[lane] = aS;
        }
    }
    gridBar(++ep, nb);

    // ---- ph7 (final): fused generation + new_ei + factored segment compute ----
    {
        int U = g_srcRank[N], P = g_kBase[N];
        int obase = 64 * U;
        for (;;) {
            int base;
            if (lane == 0) base = atomicAdd(&g_cursor, 2);
            base = __shfl_sync(0xffffffffu, base, 0);
            if (base >= N) break;
            for (int a = base; a < base + 2 && a < N; a++) {
                int cnt = g_cntKept[a];
                if (!cnt) continue;
                int da = g_curA[a];
                int dc = da > DAMAX ? DAMAX : da;
                int lo = a * DAMAX;
                for (int i = lane; i < dc; i += 32) s_uns[w][i] = g_tgtS[lo + i];
                __syncwarp();
                for (int i = lane; i < dc; i += 32) {
                    int vi = s_uns[w][i], r = 0;
                    for (int j = 0; j < dc; j++) {
                        int vj = s_uns[w][j];
                        r += (vj < vi) | ((vj == vi) & (j < i));
                    }
                    s_srt[w][r] = vi;
                }
                __syncwarp();
                for (int i = lane; i < dc; i += 32) {
                    int v = s_srt[w][i];
                    int dn = g_curA[v];
                    s_dn[w][i] = dn > DAMAX ? DAMAX : dn;
                    s_ko[w][i] = g_keep[v] ? g_keptOut[v] : 0;
                }
                __syncwarp();
                int u = g_srcRank[a];
                float ra = (float)g_rank[a];
                int p = g_kBase[a];
                float2 aB = make_float2(0.f, 0.f), aC = make_float2(0.f, 0.f);
                int idx = 0;
                while (idx < dc) {
                    int v = s_srt[w][idx];
                    int k = 1;
                    while (idx + k < dc && s_srt[w][idx + k] == v) k++;
                    int ko = s_ko[w][idx];
                    if (ko) {
                        float kf = (float)k;
                        float m = kf * (float)ko;
                        float2 xv = ((const float2*)(x + v * 64))[lane];
                        float2 so = ((const float2*)(g_Sout + v * 64))[lane];
                        aB.x += m * xv.x; aB.y += m * xv.y;
                        aC.x += kf * so.x; aC.y += kf * so.y;
                        int eb = v * DAMAX, din = s_dn[w][idx];
                        float rv = (float)g_rank[v];
                        for (int c0 = 0; c0 < din; c0 += 32) {
                            int rem = din - c0; if (rem > 32) rem = 32;
                            int wv = 0, kp = 0;
                            if (lane < rem) { wv = g_tgtS[eb + c0 + lane]; kp = g_keep[wv]; }
                            unsigned mask = __ballot_sync(0xffffffffu, kp);
                            int j = __popc(mask & ((1u << lane) - 1u));
                            if (kp) {
                                float rw = (float)g_rank[wv];
                                for (int c = 0; c < k; c++) {
                                    int pp = p + j * k + c;
                                    out[obase + pp] = ra;
                                    out[obase + P + pp] = rv;
                                    out[obase + 2 * P + pp] = rw;
                                }
                            }
                            p += k * __popc(mask);
                        }
                    }
                    idx += k;
                }
                float inv = 1.0f / (float)cnt;
                float2 xa = ((const float2*)(x + a * 64))[lane];
                sv[w][2 * lane] = xa.x;              sv[w][2 * lane + 1] = xa.y;
                sv[w][64 + 2 * lane] = aB.x * inv;   sv[w][64 + 2 * lane + 1] = aB.y * inv;
                sv[w][128 + 2 * lane] = aC.x * inv;  sv[w][128 + 2 * lane + 1] = aC.y * inv;
                __syncwarp();
                float acc0 = bvec[lane], acc1 = bvec[lane + 32];
#pragma unroll 8
                for (int i = 0; i < 64; i++) {
                    float v0 = sv[w][i], v1 = sv[w][64 + i], v2 = sv[w][128 + i];
                    int bb = i * 64 + lane;
                    acc0 += g_Wt[bb] * v0 + g_Wt[4096 + bb] * v1 + g_Wt[8192 + bb] * v2;
                    acc1 += g_Wt[bb + 32] * v0 + g_Wt[4096 + bb + 32] * v1 + g_Wt[8192 + bb + 32] * v2;
                }
                out[u * 64 + lane] = acc0;
                out[u * 64 + lane + 32] = acc1;
                __syncwarp();
            }
        }
    }
}

extern "C" void kernel_launch(void* const* d_in, const int* in_sizes, int n_in,
                              void* d_out, int out_size) {
    const float* x = (const float*)d_in[0];
    const int* ei = (const int*)d_in[1];
    const float* W = (const float*)d_in[2];
    const float* b = (const float*)d_in[3];
    float* out = (float*)d_out;
    int N = in_sizes[0] / 64;
    int E = in_sizes[1] / 2;

    int dev = 0, sms = 148;
    cudaGetDevice(&dev);
    cudaDeviceGetAttribute(&sms, cudaDevAttrMultiProcessorCount, dev);
    if (sms > MAXB) sms = MAXB;

    kInitAll<<<64, 256>>>(W);
    kMega<<<sms, 1024>>>(x, ei, b, out, N, E);
}

// round 16
// speedup vs baseline: 1.5361x; 1.0438x over previous
#include <cuda_runtime.h>

#define NS 20480
#define EMAX 120000
#define DHIST 4096
#define MAXB 160
#define DAMAX 64
#define KBW (NS / 32)

__device__ __align__(16) int g_tgtHist[NS + 8];
__device__ __align__(16) int g_curA[NS + 8];        // doubles as srcHist after ph1
__device__ __align__(16) int g_eScat[NS * DAMAX];
__device__ __align__(16) int g_tgtU[NS * DAMAX];
__device__ __align__(16) int g_tgtS[NS * DAMAX];
__device__ __align__(16) int g_prod[NS + 8];
__device__ __align__(16) int g_histTri[NS + 8];
__device__ __align__(16) int g_deg[NS + 8];
__device__ int g_deg2[NS + 8];
__device__ __align__(16) int g_keptOut[NS + 8], g_keptInK[NS + 8];
__device__ __align__(16) int g_cntKept[NS + 8];
__device__ int g_kBase[NS + 8];
__device__ __align__(16) int g_histD[DHIST + 8];
__device__ int g_cumD[DHIST + 8];
__device__ int g_maxNode, g_cursor;
__device__ __align__(16) int g_tieEx[NS + 8];
__device__ __align__(16) unsigned g_keepBits[KBW + 8];
__device__ __align__(16) int g_srcPresent[NS + 8], g_present[NS + 8];
__device__ int g_srcRank[NS + 8], g_rank[NS + 8];
__device__ float g_Wt[3 * 64 * 64];
__device__ __align__(16) float g_Sout[NS * 64];
__device__ volatile int g_arrive[MAXB * 32];
__device__ volatile int g_barPhase;
__device__ volatile int g_mini[8];

// dynamic smem layout (bytes)
#define OFF_SV    0
#define OFF_UNS   24576
#define OFF_SRT   32768
#define OFF_DN    40960
#define OFF_KO    49152
#define OFF_KR    57344
#define OFF_KB    98304
#define SMEM_TOTAL 100864

__device__ __forceinline__ void gridBar(int ep, int nb) {
    __syncthreads();
    if (blockIdx.x == 0) {
        if (threadIdx.x < 32) {
            int lane = threadIdx.x;
            if (lane == 0) { __threadfence(); g_arrive[0] = ep; }
            bool ok;
            do {
                ok = true;
                for (int s = lane; s < nb; s += 32)
                    if (g_arrive[s * 32] < ep) ok = false;
            } while (__ballot_sync(0xffffffffu, !ok));
            if (lane == 0) { __threadfence(); g_barPhase = ep; }
        }
    } else if (threadIdx.x == 0) {
        __threadfence();
        g_arrive[blockIdx.x * 32] = ep;
        while (g_barPhase < ep) __nanosleep(32);
        __threadfence();
    }
    __syncthreads();
}

__device__ __forceinline__ int blockScanEx(int v, int* tot) {
    __shared__ int s_w[32];
    __shared__ int s_tot;
    int lane = threadIdx.x & 31, wid = threadIdx.x >> 5, nw = blockDim.x >> 5;
    int inc = v;
#pragma unroll
    for (int o = 1; o < 32; o <<= 1) {
        int u = __shfl_up_sync(0xffffffffu, inc, o);
        if (lane >= o) inc += u;
    }
    if (lane == 31) s_w[wid] = inc;
    __syncthreads();
    if (wid == 0) {
        int sv2 = (lane < nw) ? s_w[lane] : 0;
        int si = sv2;
#pragma unroll
        for (int o = 1; o < 32; o <<= 1) {
            int u = __shfl_up_sync(0xffffffffu, si, o);
            if (lane >= o) si += u;
        }
        s_w[lane] = si - sv2;
        if (lane == 31) s_tot = si;
    }
    __syncthreads();
    int ex = inc - v + s_w[wid];
    *tot = s_tot;
    __syncthreads();
    return ex;
}

template <int VPT4>
__device__ void sbScanFast(const int* in, int* out, int n) {
    int v[VPT4 * 4];
    const int4* in4 = (const int4*)in;
#pragma unroll
    for (int j = 0; j < VPT4; j++) {
        int4 q = in4[threadIdx.x * VPT4 + j];
        v[4 * j] = q.x; v[4 * j + 1] = q.y; v[4 * j + 2] = q.z; v[4 * j + 3] = q.w;
    }
    int loc = 0;
#pragma unroll
    for (int j = 0; j < VPT4 * 4; j++) { int t = v[j]; v[j] = loc; loc += t; }
    int tot, ex = blockScanEx(loc, &tot);
    int base = threadIdx.x * VPT4 * 4;
#pragma unroll
    for (int j = 0; j < VPT4 * 4; j++) {
        int i = base + j;
        if (i < n) out[i] = ex + v[j];
    }
    if (threadIdx.x == 0) out[n] = tot;
}

__global__ void kInitAll(const float* __restrict__ W) {
    int i = blockIdx.x * blockDim.x + threadIdx.x;
    int gsz = gridDim.x * blockDim.x;
    for (int j = i; j < MAXB * 32; j += gsz) g_arrive[j] = 0;
    for (int j = i; j < NS; j += gsz) {
        g_tgtHist[j] = 0; g_curA[j] = 0;
        g_histTri[j] = 0; g_deg2[j] = 0;
        g_keptOut[j] = 0; g_keptInK[j] = 0; g_cntKept[j] = 0;
        g_srcPresent[j] = 0; g_present[j] = 0;
    }
    for (int j = i; j < DHIST; j += gsz) g_histD[j] = 0;
    for (int j = i; j < 12288; j += gsz) {
        int o = j & 63, ii = (j >> 6) & 63, k = j >> 12;
        g_Wt[j] = W[o * 192 + ii * 3 + k];
    }
    if (i < 8) g_mini[i] = 0;
    if (i == 0) { g_barPhase = 0; g_maxNode = -1; g_cursor = 0; }
}

__global__ void __launch_bounds__(1024, 1) kMega(
    const float* __restrict__ x, const int* __restrict__ ei,
    const float* __restrict__ bvec, float* __restrict__ out, int N, int E)
{
    extern __shared__ char dsm[];
    float (*sv)[192]   = (float(*)[192])(dsm + OFF_SV);
    int (*s_uns)[DAMAX] = (int(*)[DAMAX])(dsm + OFF_UNS);
    int (*s_srt)[DAMAX] = (int(*)[DAMAX])(dsm + OFF_SRT);
    int (*s_dn)[DAMAX]  = (int(*)[DAMAX])(dsm + OFF_DN);
    int (*s_ko)[DAMAX]  = (int(*)[DAMAX])(dsm + OFF_KO);
    unsigned short* s_kr = (unsigned short*)(dsm + OFF_KR);
    unsigned* s_kb       = (unsigned*)(dsm + OFF_KB);
    __shared__ int s_red[32];
    __shared__ int s_dstar, s_r;
    const int tid = threadIdx.x, bid = blockIdx.x, nb = gridDim.x;
    const int gsz = nb * 1024;
    const int g0 = bid * 1024 + tid;
    const int lane = tid & 31, w = tid >> 5;
    const int warpId = g0 >> 5, nwarps = nb * 32;
    int ep = 0;

    // ---- ph1: tgt histogram + bucket scatter ----
    for (int e = g0; e < E; e += gsz) {
        int s = ei[e], t = ei[E + e];
        atomicAdd(&g_tgtHist[t], 1);
        int slot = atomicAdd(&g_curA[s], 1);
        if (slot < DAMAX) {
            g_eScat[s * DAMAX + slot] = e;
            g_tgtU[s * DAMAX + slot] = t;
        }
    }
    gridBar(++ep, nb);

    // ---- ph2: warp-per-node: histTri + deg2 scatter ----
    for (int s = warpId; s < N; s += nwarps) {
        int da = g_curA[s];
        if (da == 0) continue;
        int dc = da > DAMAX ? DAMAX : da;
        int lo = s * DAMAX;
        int ih = g_tgtHist[s];
        int acc = 0;
        for (int i = lane; i < dc; i += 32) {
            int t = g_tgtU[lo + i];
            acc += g_curA[t];
            atomicAdd(&g_deg2[t], ih);
        }
#pragma unroll
        for (int o = 16; o; o >>= 1) acc += __shfl_down_sync(0xffffffffu, acc, o);
        if (lane == 0) g_histTri[s] = acc;
    }
    gridBar(++ep, nb);

    // ---- ph3: blocks 0-7: deg+histD+maxNode; mini-sync; b0: median + keep bitmap.
    //      blocks 8+: bucket stable sort ----
    if (bid < 8) {
        int chunk = (N + 7) / 8;
        int lo3 = bid * chunk, hi3 = lo3 + chunk; if (hi3 > N) hi3 = N;
        int mloc = -1;
        for (int i = lo3 + tid; i < hi3; i += 1024) {
            int d = g_histTri[i] + g_curA[i] * g_tgtHist[i] + g_deg2[i];
            g_deg[i] = d;
            int dd = d > DHIST - 1 ? DHIST - 1 : d;
            atomicAdd(&g_histD[dd], 1);
            if (d > 0 && i > mloc) mloc = i;
        }
#pragma unroll
        for (int o = 16; o; o >>= 1) {
            int u = __shfl_down_sync(0xffffffffu, mloc, o);
            if (u > mloc) mloc = u;
        }
        if (lane == 0) s_red[w] = mloc;
        __syncthreads();
        if (tid < 32) {
            int m = s_red[tid];
#pragma unroll
            for (int o = 16; o; o >>= 1) {
                int u = __shfl_down_sync(0xffffffffu, m, o);
                if (u > m) m = u;
            }
            if (tid == 0 && m >= 0) atomicMax(&g_maxNode, m);
        }
        __syncthreads();
        if (tid == 0) { __threadfence(); g_mini[bid] = 1; }
        if (bid == 0) {
            if (tid == 0) {
                bool ok;
                do {
                    ok = true;
                    for (int s = 0; s < 8; s++) if (g_mini[s] == 0) ok = false;
                } while (!ok);
                __threadfence();
            }
            __syncthreads();
            sbScanFast<1>(g_histD, g_cumD, DHIST);
            __syncthreads();
            int L = g_maxNode + 1, half = L >> 1;
            int extra = N - L;
            for (int d = tid; d < DHIST; d += 1024) {
                int lo2 = g_cumD[d] - (d > 0 ? extra : 0);
                int hi2 = g_cumD[d + 1] - extra;
                if (lo2 <= half && half < hi2) { s_dstar = d; s_r = half - lo2; }
            }
            __syncthreads();
            int dstar = s_dstar, r = s_r;
            for (int i = tid; i < NS; i += 1024)
                g_prod[i] = (i < L && g_deg[i] == dstar) ? 1 : 0;
            __syncthreads();
            sbScanFast<5>(g_prod, g_tieEx, N);
            __syncthreads();
            for (int i = tid; i < NS; i += 1024) {
                int kp = 0;
                if (i < N) {
                    kp = 1;
                    if (i < L) {
                        int d = g_deg[i];
                        if (d < dstar) kp = 0;
                        else if (d == dstar && g_tieEx[i] < r) kp = 0;
                    }
                }
                unsigned bits = __ballot_sync(0xffffffffu, kp);
                if (lane == 0) g_keepBits[i >> 5] = bits;
            }
        }
    } else {
        int warpId8 = ((bid - 8) * 1024 + tid) >> 5, nwarps8 = (nb - 8) * 32;
        for (int v = warpId8; v < N; v += nwarps8) {
            int s = g_curA[v];
            if (s == 0) continue;
            int dc = s > DAMAX ? DAMAX : s;
            int lo = v * DAMAX;
            for (int i = lane; i < dc; i += 32) s_uns[w][i] = g_eScat[lo + i];
            __syncwarp();
            for (int i = lane; i < dc; i += 32) {
                int val = s_uns[w][i], r = 0;
                for (int j = 0; j < dc; j++) r += (s_uns[w][j] < val);
                g_tgtS[lo + r] = g_tgtU[lo + i];
            }
            __syncwarp();
        }
    }
    gridBar(++ep, nb);

    // load keep bitmap to shared (persists through ph4..ph7)
    for (int j = tid; j < KBW; j += 1024) s_kb[j] = g_keepBits[j];
    __syncthreads();
#define KEEPB(i) ((s_kb[(i) >> 5] >> ((i) & 31)) & 1u)

    // ---- ph4: warp-per-kept-node: keptOut (ballot) + keptInK scatter ----
    for (int s = warpId; s < N; s += nwarps) {
        if (!KEEPB(s)) continue;
        int da = g_curA[s];
        if (da == 0) continue;
        int dc = da > DAMAX ? DAMAX : da;
        int lo = s * DAMAX;
        int kcnt = 0;
        for (int c0 = 0; c0 < dc; c0 += 32) {
            int rem = dc - c0; if (rem > 32) rem = 32;
            int t = 0, kp = 0;
            if (lane < rem) { t = g_tgtS[lo + c0 + lane]; kp = KEEPB(t); }
            unsigned mask = __ballot_sync(0xffffffffu, kp);
            kcnt += __popc(mask);
            if (kp) atomicAdd(&g_keptInK[t], 1);
        }
        if (lane == 0) g_keptOut[s] = kcnt;
    }
    gridBar(++ep, nb);

    // ---- ph5: warp-per-kept-node: cntKept + present flags ----
    for (int s = warpId; s < N; s += nwarps) {
        if (!KEEPB(s)) continue;
        int da = g_curA[s];
        int dc = da > DAMAX ? DAMAX : da;
        int lo = s * DAMAX;
        int cnt = 0;
        int sInK = g_keptInK[s];
        for (int c0 = 0; c0 < dc; c0 += 32) {
            int rem = dc - c0; if (rem > 32) rem = 32;
            int t = 0, kp = 0;
            if (lane < rem) { t = g_tgtS[lo + c0 + lane]; kp = KEEPB(t); }
            if (kp) {
                cnt += g_keptOut[t];
                if (sInK) g_present[t] = 1;
            }
        }
#pragma unroll
        for (int o = 16; o; o >>= 1) cnt += __shfl_down_sync(0xffffffffu, cnt, o);
        cnt = __shfl_sync(0xffffffffu, cnt, 0);
        if (lane == 0) {
            g_cntKept[s] = cnt;
            if (cnt > 0) { g_present[s] = 1; g_srcPresent[s] = 1; }
            if (g_keptOut[s] && sInK) g_present[s] = 1;
        }
    }
    gridBar(++ep, nb);

    // ---- ph6: three scans on blocks 0-2; blocks 3+: Sout for kept nodes ----
    if (bid == 0) sbScanFast<5>(g_cntKept, g_kBase, N);
    else if (bid == 1) sbScanFast<5>(g_srcPresent, g_srcRank, N);
    else if (bid == 2) sbScanFast<5>(g_present, g_rank, N);
    else {
        int warpId3 = ((bid - 3) * 1024 + tid) >> 5, nwarps3 = (nb - 3) * 32;
        for (int v = warpId3; v < N; v += nwarps3) {
            if (!KEEPB(v)) continue;
            int da = g_curA[v];
            if (da == 0) continue;
            int dc = da > DAMAX ? DAMAX : da;
            int lo = v * DAMAX;
            float2 aS = make_float2(0.f, 0.f);
            int any = 0;
            for (int c0 = 0; c0 < dc; c0 += 32) {
                int rem = dc - c0; if (rem > 32) rem = 32;
                int wv = 0, kp = 0;
                if (lane < rem) { wv = g_tgtS[lo + c0 + lane]; kp = KEEPB(wv); }
                unsigned mask = __ballot_sync(0xffffffffu, kp);
                any |= mask;
                while (mask) {
                    int j = __ffs(mask) - 1; mask &= mask - 1;
                    int wvj = __shfl_sync(0xffffffffu, wv, j);
                    float2 xx = ((const float2*)(x + wvj * 64))[lane];
                    aS.x += xx.x; aS.y += xx.y;
                }
            }
            if (any) ((float2*)(g_Sout + v * 64))[lane] = aS;
        }
    }
    gridBar(++ep, nb);

    // build packed keep|rank table (rank < 2^15)
    for (int i = tid; i < N; i += 1024)
        s_kr[i] = (unsigned short)((KEEPB(i) << 15) | (unsigned)g_rank[i]);
    __syncthreads();

    // ---- ph7 (final): fused generation + new_ei + factored segment compute ----
    {
        int U = g_srcRank[N], P = g_kBase[N];
        int obase = 64 * U;
        for (;;) {
            int base;
            if (lane == 0) base = atomicAdd(&g_cursor, 2);
            base = __shfl_sync(0xffffffffu, base, 0);
            if (base >= N) break;
            for (int a = base; a < base + 2 && a < N; a++) {
                int cnt = g_cntKept[a];
                if (!cnt) continue;
                int da = g_curA[a];
                int dc = da > DAMAX ? DAMAX : da;
                int lo = a * DAMAX;
                for (int i = lane; i < dc; i += 32) s_uns[w][i] = g_tgtS[lo + i];
                __syncwarp();
                for (int i = lane; i < dc; i += 32) {
                    int vi = s_uns[w][i], r = 0;
                    for (int j = 0; j < dc; j++) {
                        int vj = s_uns[w][j];
                        r += (vj < vi) | ((vj == vi) & (j < i));
                    }
                    s_srt[w][r] = vi;
                }
                __syncwarp();
                for (int i = lane; i < dc; i += 32) {
                    int v = s_srt[w][i];
                    int dn = g_curA[v];
                    s_dn[w][i] = dn > DAMAX ? DAMAX : dn;
                    s_ko[w][i] = (s_kr[v] >> 15) ? g_keptOut[v] : 0;
                }
                __syncwarp();
                int u = g_srcRank[a];
                float ra = (float)(s_kr[a] & 0x7fffu);
                int p = g_kBase[a];
                float2 aB = make_float2(0.f, 0.f), aC = make_float2(0.f, 0.f);
                int idx = 0;
                while (idx < dc) {
                    int v = s_srt[w][idx];
                    int k = 1;
                    while (idx + k < dc && s_srt[w][idx + k] == v) k++;
                    int ko = s_ko[w][idx];
                    if (ko) {
                        float kf = (float)k;
                        float m = kf * (float)ko;
                        float2 xv = ((const float2*)(x + v * 64))[lane];
                        float2 so = ((const float2*)(g_Sout + v * 64))[lane];
                        aB.x += m * xv.x; aB.y += m * xv.y;
                        aC.x += kf * so.x; aC.y += kf * so.y;
                        int eb = v * DAMAX, din = s_dn[w][idx];
                        float rv = (float)(s_kr[v] & 0x7fffu);
                        for (int c0 = 0; c0 < din; c0 += 32) {
                            int rem = din - c0; if (rem > 32) rem = 32;
                            int wv = 0, kp = 0;
                            unsigned short krw = 0;
                            if (lane < rem) {
                                wv = g_tgtS[eb + c0 + lane];
                                krw = s_kr[wv];
                                kp = krw >> 15;
                            }
                            unsigned mask = __ballot_sync(0xffffffffu, kp);
                            int j = __popc(mask & ((1u << lane) - 1u));
                            if (kp) {
                                float rw = (float)(krw & 0x7fffu);
                                for (int c = 0; c < k; c++) {
                                    int pp = p + j * k + c;
                                    out[obase + pp] = ra;
                                    out[obase + P + pp] = rv;
                                    out[obase + 2 * P + pp] = rw;
                                }
                            }
                            p += k * __popc(mask);
                        }
                    }
                    idx += k;
                }
                float inv = 1.0f / (float)cnt;
                float2 xa = ((const float2*)(x + a * 64))[lane];
                sv[w][2 * lane] = xa.x;              sv[w][2 * lane + 1] = xa.y;
                sv[w][64 + 2 * lane] = aB.x * inv;   sv[w][64 + 2 * lane + 1] = aB.y * inv;
                sv[w][128 + 2 * lane] = aC.x * inv;  sv[w][128 + 2 * lane + 1] = aC.y * inv;
                __syncwarp();
                float acc0 = bvec[lane], acc1 = bvec[lane + 32];
#pragma unroll 8
                for (int i = 0; i < 64; i++) {
                    float v0 = sv[w][i], v1 = sv[w][64 + i], v2 = sv[w][128 + i];
                    int bb = i * 64 + lane;
                    acc0 += g_Wt[bb] * v0 + g_Wt[4096 + bb] * v1 + g_Wt[8192 + bb] * v2;
                    acc1 += g_Wt[bb + 32] * v0 + g_Wt[4096 + bb + 32] * v1 + g_Wt[8192 + bb + 32] * v2;
                }
                out[u * 64 + lane] = acc0;
                out[u * 64 + lane + 32] = acc1;
                __syncwarp();
            }
        }
    }
}

extern "C" void kernel_launch(void* const* d_in, const int* in_sizes, int n_in,
                              void* d_out, int out_size) {
    const float* x = (const float*)d_in[0];
    const int* ei = (const int*)d_in[1];
    const float* W = (const float*)d_in[2];
    const float* b = (const float*)d_in[3];
    float* out = (float*)d_out;
    int N = in_sizes[0] / 64;
    int E = in_sizes[1] / 2;

    int dev = 0, sms = 148;
    cudaGetDevice(&dev);
    cudaDeviceGetAttribute(&sms, cudaDevAttrMultiProcessorCount, dev);
    if (sms > MAXB) sms = MAXB;

    cudaFuncSetAttribute(kMega, cudaFuncAttributeMaxDynamicSharedMemorySize, SMEM_TOTAL);
    kInitAll<<<64, 256>>>(W);
    kMega<<<sms, 1024, SMEM_TOTAL>>>(x, ei, b, out, N, E);
}